// round 15
// baseline (speedup 1.0000x reference)
#include <cuda_runtime.h>
#include <cuda_bf16.h>
#include <cstdint>

#define Bc   2
#define Nc   4096
#define Kc   16
#define CINc 128
#define Dc   256
#define PHc  64
#define AHc  1024
#define Pc   (Nc*Kc)   /* 65536 */
#define EPSc 1e-5f
#define NCH  8
#define CH   512

typedef unsigned long long ull;

// ---------------- packed f32x2 helpers (used in build) ----------------
__device__ __forceinline__ ull pk2(float a, float b){
    ull r; asm("mov.b64 %0,{%1,%2};" : "=l"(r) : "f"(a), "f"(b)); return r;
}
__device__ __forceinline__ void upk2(ull v, float& a, float& b){
    asm("mov.b64 {%0,%1},%2;" : "=f"(a), "=f"(b) : "l"(v));
}
__device__ __forceinline__ ull fma2(ull a, ull b, ull c){
    ull d; asm("fma.rn.f32x2 %0,%1,%2,%3;" : "=l"(d) : "l"(a), "l"(b), "l"(c)); return d;
}

__device__ __forceinline__ uint32_t smem_u32(const void* p){
    uint32_t a; asm("{ .reg .u64 t; cvta.to.shared.u64 t, %1; cvt.u32.u64 %0, t; }" : "=r"(a) : "l"(p));
    return a;
}

// ---------------- warp-MMA + cp.async helpers ----------------
#define LDSM_X4(r, a) \
    asm volatile("ldmatrix.sync.aligned.m8n8.x4.shared.b16 {%0,%1,%2,%3}, [%4];" \
        : "=r"((r)[0]), "=r"((r)[1]), "=r"((r)[2]), "=r"((r)[3]) : "r"(a))

#define MMA16816(d, a, b0, b1) \
    asm volatile("mma.sync.aligned.m16n8k16.row.col.f32.bf16.bf16.f32 " \
        "{%0,%1,%2,%3},{%4,%5,%6,%7},{%8,%9},{%0,%1,%2,%3};" \
        : "+f"((d)[0]), "+f"((d)[1]), "+f"((d)[2]), "+f"((d)[3]) \
        : "r"((a)[0]), "r"((a)[1]), "r"((a)[2]), "r"((a)[3]), "r"(b0), "r"(b1))

#define CP_ASYNC16(dst, src) \
    asm volatile("cp.async.cg.shared.global [%0], [%1], 16;" :: "r"(dst), "l"(src))
#define CP_COMMIT() asm volatile("cp.async.commit_group;" ::: "memory")
#define CP_WAIT2()  asm volatile("cp.async.wait_group 2;" ::: "memory")
#define CP_WAIT1()  asm volatile("cp.async.wait_group 1;" ::: "memory")
#define CP_WAIT0()  asm volatile("cp.async.wait_group 0;" ::: "memory")
#define STS32(a, v) asm volatile("st.shared.u32 [%0], %1;" :: "r"(a), "r"(v) : "memory")

// ---------------- device scratch ----------------
__device__ float g_Wk[Dc*CINc], g_Wv[Dc*CINc], g_Wq[Dc*CINc];
__device__ float g_bk2[Dc], g_bv2[Dc], g_bq2[Dc];
__device__ float g_Wa1f[AHc*Dc];
__device__ float g_ba1f[AHc];
__device__ float g_Wp1f[PHc*3];
__device__ float g_bp1f[PHc];
__device__ __nv_bfloat16 g_Wa2h[Dc*AHc];   // [c][j] row-major
__device__ __nv_bfloat16 g_W12h[AHc*PHc];  // composed Wa1f@Wp2, [j][t]
__device__ float g_b1p[AHc];               // ba1f + Wa1f@bp2
__device__ __nv_bfloat16 g_WAQ[AHc*CINc];  // Wa1f@Wq_c, [j][c]
__device__ __nv_bfloat16 g_WAK[AHc*CINc];  // Wa1f@Wk_c
__device__ float g_bqk[AHc];               // Wa1f@(bq2-bk2)
__device__ __nv_bfloat16 g_qp_h[Bc*Nc*CINc];   // (b,n,c) bf16 transposed input
__device__ __nv_bfloat16 g_obj_h[Bc*Nc*CINc];
__device__ float g_valv[Bc*Nc*Dc];  // point-major
__device__ __nv_bfloat16 g_qWh[(size_t)Bc*Nc*AHc];  // WAQ·qp per point, bf16
__device__ __nv_bfloat16 g_kWh[(size_t)Bc*Nc*AHc];  // WAK·obj per point, bf16
__device__ int   g_idx[Bc*Nc*Kc];
__device__ float g_pd[(size_t)Bc*NCH*Nc*16];
__device__ int   g_pi[(size_t)Bc*NCH*Nc*16];
__device__ __nv_bfloat16 g_hh[(size_t)Bc*Pc*PHc]; // (b,p,t) relu pos hidden, bf16
__device__ float g_PE[(size_t)Bc*Pc*Dc];          // (b,p,c) fp32: pe
__device__ float g_agg[Bc*Dc*Nc];                 // (b,c,n)

// ---------------- input transpose: (b,c,n) fp32 -> (b,n,c) bf16 ----------------
__global__ void transpose_in_kernel(const float* __restrict__ qp, const float* __restrict__ obj)
{
    __shared__ float t[128][33];
    int z = blockIdx.y; int b = z >> 1; int which = z & 1;
    const float* In = which ? obj : qp;
    __nv_bfloat16* Out = which ? g_obj_h : g_qp_h;
    int n0 = blockIdx.x*32;
    int tid = threadIdx.x;
    int nn = tid & 31, c8 = tid >> 5;
    #pragma unroll
    for (int i = 0; i < 16; i++) {
        int c = c8*16 + i;
        t[c][nn] = In[((size_t)b*CINc + c)*Nc + n0 + nn];
    }
    __syncthreads();
    int c = tid & 127, r2 = tid >> 7;
    #pragma unroll
    for (int i = 0; i < 16; i++) {
        int nr = r2*16 + i;
        Out[((size_t)b*Nc + n0 + nr)*CINc + c] = __float2bfloat16(t[c][nr]);
    }
}

// ---------------- tiled small GEMM: C[M x N] = A[M x K] @ B[K x N] ----------------
// A,B row-major fp32. Out fp32 (Cf) or bf16 (Ch), row-major. grid (N/64, M/64), 256 thr.
template<int KT>
__global__ void cgemm_kernel(const float* __restrict__ A, const float* __restrict__ B,
                             float* __restrict__ Cf, __nv_bfloat16* __restrict__ Ch, int N)
{
    __shared__ float Wt[64][33];
    __shared__ float Xt[32][65];
    int n0 = blockIdx.x*64, m0 = blockIdx.y*64;
    int tid = threadIdx.x, tx = tid & 15, ty = tid >> 4;
    float acc[4][4];
    #pragma unroll
    for (int r = 0; r < 4; r++)
        #pragma unroll
        for (int c = 0; c < 4; c++) acc[r][c] = 0.f;

    for (int k0 = 0; k0 < KT; k0 += 32) {
        for (int q = tid; q < 64*32; q += 256) {
            int mm = q >> 5, kk = q & 31;
            Wt[mm][kk] = A[(size_t)(m0+mm)*KT + k0 + kk];
        }
        for (int q = tid; q < 32*64; q += 256) {
            int kk = q >> 6, nn = q & 63;
            Xt[kk][nn] = B[(size_t)(k0+kk)*N + n0 + nn];
        }
        __syncthreads();
        #pragma unroll 8
        for (int kk = 0; kk < 32; kk++) {
            float a[4], bb[4];
            #pragma unroll
            for (int r = 0; r < 4; r++) a[r]  = Wt[ty*4+r][kk];
            #pragma unroll
            for (int c = 0; c < 4; c++) bb[c] = Xt[kk][tx*4+c];
            #pragma unroll
            for (int r = 0; r < 4; r++)
                #pragma unroll
                for (int c = 0; c < 4; c++) acc[r][c] = fmaf(a[r], bb[c], acc[r][c]);
        }
        __syncthreads();
    }
    #pragma unroll
    for (int r = 0; r < 4; r++) {
        int mm = m0 + ty*4 + r;
        #pragma unroll
        for (int c = 0; c < 4; c++) {
            int nn = n0 + tx*4 + c;
            if (Ch) Ch[(size_t)mm*N + nn] = __float2bfloat16(acc[r][c]);
            else    Cf[(size_t)mm*N + nn] = acc[r][c];
        }
    }
}

// ---------------- compose biases: bk2/bv2/bq2 (raw inputs) ----------------
__global__ void compose_bias_kernel(const float* __restrict__ Wk, const float* __restrict__ bk,
                                    const float* __restrict__ Wq, const float* __restrict__ bq,
                                    const float* __restrict__ Wv, const float* __restrict__ bv,
                                    const float* __restrict__ b_lsq, const float* __restrict__ b_lso)
{
    int id = blockIdx.x*256 + threadIdx.x;
    if (id >= 3*Dc) return;
    int which = id / Dc, o = id % Dc;
    const float* A  = (which==0) ? Wk : ((which==1) ? Wv : Wq);
    const float* bb = (which==0) ? bk : ((which==1) ? bv : bq);
    const float* lb = (which==2) ? b_lsq : b_lso;
    float s = bb[o];
    #pragma unroll 4
    for (int t = 0; t < Dc; t++) s = fmaf(A[o*Dc+t], lb[t], s);
    float* Od = (which==0) ? g_bk2 : ((which==1) ? g_bv2 : g_bq2);
    Od[o] = s;
}

// ---------------- BN folding ----------------
__global__ void fold_kernel(const float* __restrict__ Wa1, const float* __restrict__ ba1,
                            const float* __restrict__ g2,  const float* __restrict__ bt2,
                            const float* __restrict__ m2,  const float* __restrict__ v2,
                            const float* __restrict__ Wp1, const float* __restrict__ bp1,
                            const float* __restrict__ g1,  const float* __restrict__ bt1,
                            const float* __restrict__ m1,  const float* __restrict__ v1)
{
    int id = blockIdx.x*256 + threadIdx.x;
    if (id < AHc*Dc) {
        int j = id / Dc;
        float sc = g2[j] * rsqrtf(v2[j] + EPSc);
        g_Wa1f[id] = sc * Wa1[id];
        return;
    }
    int r = id - AHc*Dc;
    if (r < AHc) {
        float sc = g2[r] * rsqrtf(v2[r] + EPSc);
        g_ba1f[r] = sc*ba1[r] + bt2[r] - m2[r]*sc;
        return;
    }
    r -= AHc;
    if (r < PHc*3) {
        int j = r / 3;
        float sc = g1[j] * rsqrtf(v1[j] + EPSc);
        g_Wp1f[r] = sc * Wp1[r];
        return;
    }
    r -= PHc*3;
    if (r < PHc) {
        float sc = g1[r] * rsqrtf(v1[r] + EPSc);
        g_bp1f[r] = sc*bp1[r] + bt1[r] - m1[r]*sc;
    }
}

// ---------------- bf16 Wa2 ----------------
__global__ void tobf16_kernel(const float* __restrict__ Wa2)
{
    int i = blockIdx.x*256 + threadIdx.x;
    if (i < AHc*Dc) g_Wa2h[i] = __float2bfloat16(Wa2[i]);
}

// ---------------- bias2: b1p = ba1f + Wa1f@bp2 ; bqk = Wa1f@(bq2-bk2) ----------------
__global__ void bias2_kernel(const float* __restrict__ bp2)
{
    int id = blockIdx.x*256 + threadIdx.x;
    if (id < AHc) {
        float s = g_ba1f[id];
        #pragma unroll 4
        for (int c = 0; c < Dc; c++) s = fmaf(g_Wa1f[id*Dc + c], bp2[c], s);
        g_b1p[id] = s;
    } else if (id < 2*AHc) {
        int j = id - AHc;
        float s = 0.f;
        #pragma unroll 4
        for (int t = 0; t < Dc; t++) s = fmaf(g_Wa1f[j*Dc + t], g_bq2[t] - g_bk2[t], s);
        g_bqk[j] = s;
    }
}

// ---------------- KNN part 1 ----------------
__global__ void knn_part_kernel(const float* __restrict__ pos)
{
    __shared__ __align__(16) float4 sc[CH];
    int b = blockIdx.z, ch = blockIdx.y;
    int tid = threadIdx.x;
    int c0 = ch * CH;
    for (int q = tid; q < CH; q += 128) {
        float x = pos[(b*3+0)*Nc + c0 + q];
        float y = pos[(b*3+1)*Nc + c0 + q];
        float z = pos[(b*3+2)*Nc + c0 + q];
        sc[q] = make_float4(x, y, z, fmaf(z, z, fmaf(y, y, x*x)));
    }
    __syncthreads();
    int n = blockIdx.x*128 + tid;
    float qx = pos[(b*3+0)*Nc + n];
    float qy = pos[(b*3+1)*Nc + n];
    float qz = pos[(b*3+2)*Nc + n];
    float qs = fmaf(qz, qz, fmaf(qy, qy, qx*qx));

    float bd[16]; int bi[16];
    #pragma unroll
    for (int t = 0; t < 16; t++) { bd[t] = 3.4e38f; bi[t] = 0; }
    float mx = 3.4e38f; int mp = 0;
    for (int m = 0; m < CH; m++) {
        float4 c = sc[m];
        float dot = fmaf(qz, c.z, fmaf(qy, c.y, qx*c.x));
        float d = (qs + c.w) - 2.0f*dot;
        if (d < mx) {
            bd[mp] = d; bi[mp] = c0 + m;
            mx = bd[0]; mp = 0;
            #pragma unroll
            for (int t = 1; t < 16; t++) if (bd[t] > mx) { mx = bd[t]; mp = t; }
        }
    }
    size_t base = ((size_t)(b*NCH + ch)*Nc + n)*16;
    #pragma unroll
    for (int t = 0; t < 16; t++) { g_pd[base + t] = bd[t]; g_pi[base + t] = bi[t]; }
}

// ---------------- KNN part 2: merge ----------------
__global__ void knn_merge_kernel()
{
    int id = blockIdx.x*256 + threadIdx.x;
    int b = id >> 12, n = id & (Nc-1);
    float bd[16]; int bi[16];
    #pragma unroll
    for (int t = 0; t < 16; t++) { bd[t] = 3.4e38f; bi[t] = 0; }
    float mx = 3.4e38f; int mp = 0;
    for (int ch = 0; ch < NCH; ch++) {
        size_t base = ((size_t)(b*NCH + ch)*Nc + n)*16;
        #pragma unroll
        for (int t = 0; t < 16; t++) {
            float d = g_pd[base + t];
            if (d < mx) {
                bd[mp] = d; bi[mp] = g_pi[base + t];
                mx = bd[0]; mp = 0;
                #pragma unroll
                for (int u = 1; u < 16; u++) if (bd[u] > mx) { mx = bd[u]; mp = u; }
            }
        }
    }
    #pragma unroll
    for (int t = 0; t < 16; t++) g_idx[(b*Nc+n)*16 + t] = bi[t];
}

// ---------------- tiled fp32 GEMM (value conv + final conv) ----------------
template<int O, int I, bool POINT_MAJOR>
__global__ void gemm_kernel(const float* __restrict__ W, const float* __restrict__ bias,
                            const float* __restrict__ In, float* __restrict__ Out)
{
    __shared__ float Wt[64][33];
    __shared__ float Xt[32][64];
    int b  = blockIdx.z;
    int n0 = blockIdx.x*64, o0 = blockIdx.y*64;
    int tid = threadIdx.x, tx = tid & 15, ty = tid >> 4;
    float acc[4][4];
    #pragma unroll
    for (int r = 0; r < 4; r++)
        #pragma unroll
        for (int c = 0; c < 4; c++) acc[r][c] = 0.f;

    for (int k0 = 0; k0 < I; k0 += 32) {
        for (int q = tid; q < 64*32; q += 256) {
            int oo = q >> 5, kk = q & 31;
            Wt[oo][kk] = W[(o0+oo)*I + k0 + kk];
        }
        for (int q = tid; q < 32*64; q += 256) {
            int kk = q >> 6, nn = q & 63;
            Xt[kk][nn] = In[((size_t)b*I + k0 + kk)*Nc + n0 + nn];
        }
        __syncthreads();
        #pragma unroll 8
        for (int kk = 0; kk < 32; kk++) {
            float a[4], bb[4];
            #pragma unroll
            for (int r = 0; r < 4; r++) a[r]  = Wt[ty*4+r][kk];
            #pragma unroll
            for (int c = 0; c < 4; c++) bb[c] = Xt[kk][tx*4+c];
            #pragma unroll
            for (int r = 0; r < 4; r++)
                #pragma unroll
                for (int c = 0; c < 4; c++) acc[r][c] = fmaf(a[r], bb[c], acc[r][c]);
        }
        __syncthreads();
    }
    #pragma unroll
    for (int r = 0; r < 4; r++) {
        float bv = bias[o0 + ty*4 + r];
        #pragma unroll
        for (int c = 0; c < 4; c++) {
            float v = acc[r][c] + bv;
            int oo = o0 + ty*4 + r, nn = n0 + tx*4 + c;
            if (POINT_MAJOR)
                Out[((size_t)b*Nc + nn)*O + oo] = v;
            else
                Out[((size_t)b*O + oo)*Nc + nn] = v;
        }
    }
}

// ---------------- build: pos-MLP hidden h (bf16) + PE (fp32) ----------------
__global__ void build_kernel(const float* __restrict__ pos,
                             const float* __restrict__ Wp2,
                             const float* __restrict__ bp2)
{
    __shared__ float pr[3][64];
    __shared__ __align__(16) float sh[PHc*64];
    __shared__ int sidx[64];
    int b = blockIdx.y;
    int nbase = blockIdx.x*4;
    int pbase = nbase*16;
    int tid = threadIdx.x;

    if (tid < 64) sidx[tid] = g_idx[(b*Nc + nbase)*16 + tid];
    __syncthreads();
    if (tid < 192) {
        int d = tid >> 6, pp = tid & 63;
        int n  = nbase + (pp >> 4);
        int nb = sidx[pp];
        pr[d][pp] = pos[(b*3+d)*Nc + n] - pos[(b*3+d)*Nc + nb];
    }
    __syncthreads();
    for (int q = tid; q < PHc*64; q += 256) {
        int j = q >> 6, pp = q & 63;
        float h = fmaf(g_Wp1f[j*3+2], pr[2][pp],
                  fmaf(g_Wp1f[j*3+1], pr[1][pp],
                  fmaf(g_Wp1f[j*3+0], pr[0][pp], g_bp1f[j])));
        sh[q] = fmaxf(h, 0.f);
    }
    __syncthreads();

    for (int q = tid; q < PHc*64; q += 256) {
        int pp = q >> 6, j = q & 63;
        g_hh[((size_t)b*Pc + pbase + pp)*PHc + j] = __float2bfloat16(sh[j*64 + pp]);
    }

    int c = tid;
    float bc = bp2[c];
    ull A[32];
    #pragma unroll
    for (int g = 0; g < 32; g++) A[g] = pk2(bc, bc);
    const ull* HP = (const ull*)sh;
    #pragma unroll 2
    for (int j = 0; j < PHc; j++) {
        float w = Wp2[c*PHc + j];
        ull wb = pk2(w, w);
        const ull* hp = HP + j*32;
        #pragma unroll
        for (int g = 0; g < 32; g++) A[g] = fma2(wb, hp[g], A[g]);
    }
    #pragma unroll
    for (int g = 0; g < 32; g++) {
        float p0, p1; upk2(A[g], p0, p1);
        g_PE[((size_t)b*Pc + pbase + g*2)*Dc + c]     = p0;
        g_PE[((size_t)b*Pc + pbase + g*2 + 1)*Dc + c] = p1;
    }
}

// ---------------- warp-MMA core with 3-stage cp.async pipeline (qkw) ----------------
#define SMPITCH 144
#define ABUF (128*SMPITCH)
#define BBUF (256*SMPITCH)
#define SMEM_MMA (3*(ABUF+BBUF))   /* 165888 B */

template<int KTOT>
__device__ __forceinline__ void mma_core(char* sm,
                                         const __nv_bfloat16* __restrict__ gA,
                                         const __nv_bfloat16* __restrict__ gB,
                                         float (&acc)[16][4])
{
    uint32_t sA = smem_u32(sm);
    uint32_t sB = sA + 3*ABUF;
    int tid = threadIdx.x;
    int lane = tid & 31, wid = tid >> 5;
    int wr = wid >> 1, wc = wid & 1;

    uint32_t aOff = (uint32_t)(wr*16 + (lane & 15))*SMPITCH + (uint32_t)((lane >> 4) << 4);
    uint32_t bOff = (uint32_t)(wc*128 + (lane & 15))*SMPITCH + (uint32_t)((lane >> 4) << 4);

    const int NS = KTOT/64;
    int arow = tid >> 3, ac8 = (tid & 7) << 3;
    #define MMA_ISSUE(s, buf) do { \
        uint32_t dA = sA + (buf)*ABUF; \
        uint32_t dB = sB + (buf)*BBUF; \
        _Pragma("unroll") \
        for (int it = 0; it < 2; it++) { \
            int row = arow + it*64; \
            CP_ASYNC16(dA + row*SMPITCH + ac8*2, gA + (size_t)row*KTOT + (s)*64 + ac8); \
        } \
        _Pragma("unroll") \
        for (int it = 0; it < 4; it++) { \
            int row = arow + it*64; \
            CP_ASYNC16(dB + row*SMPITCH + ac8*2, gB + (size_t)row*KTOT + (s)*64 + ac8); \
        } \
        CP_COMMIT(); \
    } while(0)

    MMA_ISSUE(0, 0);
    if (NS > 1) MMA_ISSUE(1, 1);
    int buf = 0;
    for (int i = 0; i < NS; i++) {
        if (i + 2 < NS)      { MMA_ISSUE(i+2, (buf+2 >= 3) ? buf-1 : buf+2); CP_WAIT2(); }
        else if (i + 1 < NS) { CP_WAIT1(); }
        else                 { CP_WAIT0(); }
        __syncthreads();
        uint32_t aAddr = sA + buf*ABUF + aOff;
        uint32_t bAddr = sB + buf*BBUF + bOff;
        #pragma unroll
        for (int ks = 0; ks < 4; ks++) {
            uint32_t a[4];
            LDSM_X4(a, aAddr + ks*32);
            #pragma unroll
            for (int tp = 0; tp < 8; tp++) {
                uint32_t q[4];
                LDSM_X4(q, bAddr + tp*16*SMPITCH + ks*32);
                MMA16816(acc[2*tp],   a, q[0], q[2]);
                MMA16816(acc[2*tp+1], a, q[1], q[3]);
            }
        }
        __syncthreads();
        buf = (buf + 1 >= 3) ? 0 : buf + 1;
    }
    #undef MMA_ISSUE
}

// ---------------- qkw: qW = WAQ·qp, kW = WAK·obj per point (K=128), bf16 out ----------------
__global__ void __launch_bounds__(512, 1) qkw_kernel()
{
    extern __shared__ __align__(16) char smq[];
    int z = blockIdx.z;
    int b = z >> 1, which = z & 1;
    int ntile = blockIdx.x*128;
    int j0 = blockIdx.y*256;
    const __nv_bfloat16* gA = (which ? g_qp_h : g_obj_h) + ((size_t)b*Nc + ntile)*CINc;
    const __nv_bfloat16* gB = (which ? g_WAQ : g_WAK) + (size_t)j0*CINc;
    __nv_bfloat16* Out = (which ? g_qWh : g_kWh) + ((size_t)b*Nc)*AHc;

    float acc[16][4];
    #pragma unroll
    for (int t = 0; t < 16; t++)
        #pragma unroll
        for (int q = 0; q < 4; q++) acc[t][q] = 0.f;

    mma_core<CINc>(smq, gA, gB, acc);

    int tid = threadIdx.x, lane = tid & 31, wid = tid >> 5;
    int wr = wid >> 1, wc = wid & 1;
    int row0 = ntile + wr*16 + (lane >> 2);
    __nv_bfloat16* O0 = Out + (size_t)row0*AHc + j0;
    __nv_bfloat16* O1 = O0 + (size_t)8*AHc;
    #pragma unroll
    for (int t = 0; t < 16; t++) {
        int c = wc*128 + t*8 + ((lane & 3) << 1);
        uint32_t u0, u1;
        asm("cvt.rn.bf16x2.f32 %0, %1, %2;" : "=r"(u0) : "f"(acc[t][1]), "f"(acc[t][0]));
        asm("cvt.rn.bf16x2.f32 %0, %1, %2;" : "=r"(u1) : "f"(acc[t][3]), "f"(acc[t][2]));
        *(uint32_t*)(O0 + c) = u0;
        *(uint32_t*)(O1 + c) = u1;
    }
}

// ---------------- FUSED mlp ----------------
#define PITCH_H 272                 /* 128 bf16 + 8 pad */
#define FA  (128*SMPITCH)
#define FW  (128*SMPITCH)
#define FH  (128*PITCH_H)
#define FB2 (256*PITCH_H)
#define SMEM_FUSED (FA + 2*FW + FH + 2*FB2)   /* 229376 B */

__global__ void __launch_bounds__(512, 1) mlp_fused_kernel()
{
    extern __shared__ __align__(16) char smf[];
    int b = blockIdx.z;
    int ptile = blockIdx.x*128;
    const __nv_bfloat16* gA = g_hh + ((size_t)b*Pc + ptile)*PHc;

    uint32_t sA  = smem_u32(smf);
    uint32_t sW  = sA + FA;
    uint32_t sH  = sW + 2*FW;
    uint32_t sB2 = sH + FH;
    int tid = threadIdx.x;
    int lane = tid & 31, wid = tid >> 5;
    int wr = wid >> 1, wc = wid & 1;

    #define FISSUE(jc_, buf_) do { \
        uint32_t dW = sW + (buf_)*FW; \
        uint32_t dB = sB2 + (buf_)*FB2; \
        int j0_ = (jc_)*128; \
        _Pragma("unroll") \
        for (int it = 0; it < 2; it++) { \
            int u = tid + it*512; int row = u >> 3, c8 = (u & 7) << 3; \
            CP_ASYNC16(dW + row*SMPITCH + c8*2, g_W12h + (size_t)(j0_ + row)*PHc + c8); \
        } \
        _Pragma("unroll") \
        for (int it = 0; it < 8; it++) { \
            int u = tid + it*512; int row = u >> 4, c8 = (u & 15) << 3; \
            CP_ASYNC16(dB + row*PITCH_H + c8*2, g_Wa2h + (size_t)row*AHc + j0_ + c8); \
        } \
        CP_COMMIT(); \
    } while(0)

    {
        #pragma unroll
        for (int it = 0; it < 2; it++) {
            int u = tid + it*512; int row = u >> 3, c8 = (u & 7) << 3;
            CP_ASYNC16(sA + row*SMPITCH + c8*2, gA + (size_t)row*PHc + c8);
        }
    }
    FISSUE(0, 0);
    FISSUE(1, 1);

    float accL[16][4];
    #pragma unroll
    for (int t = 0; t < 16; t++)
        #pragma unroll
        for (int q = 0; q < 4; q++) accL[t][q] = 0.f;

    int n = (ptile >> 4) + wr;
    int k0i = lane >> 2;
    int nb0 = g_idx[(b*Nc + n)*16 + k0i];
    int nb1 = g_idx[(b*Nc + n)*16 + k0i + 8];
    const __nv_bfloat16* qWrow = g_qWh + ((size_t)b*Nc + n)*AHc;
    const __nv_bfloat16* kW0   = g_kWh + ((size_t)b*Nc + nb0)*AHc;
    const __nv_bfloat16* kW1   = g_kWh + ((size_t)b*Nc + nb1)*AHc;

    uint32_t aOff1 = (uint32_t)(wr*16 + (lane & 15))*SMPITCH + (uint32_t)((lane >> 4) << 4);
    uint32_t bOff1 = (uint32_t)(wc*64 + (lane & 15))*SMPITCH + (uint32_t)((lane >> 4) << 4);
    uint32_t aOff2 = (uint32_t)(wr*16 + (lane & 15))*PITCH_H + (uint32_t)((lane >> 4) << 4);
    uint32_t bOff2 = (uint32_t)(wc*128 + (lane & 15))*PITCH_H + (uint32_t)((lane >> 4) << 4);
    uint32_t hRow0 = sH + (uint32_t)(wr*16 + (lane >> 2))*PITCH_H;
    uint32_t hRow1 = hRow0 + 8*PITCH_H;

    for (int jc = 0; jc < 8; jc++) {
        int j0 = jc*128;
        if (jc < 7) CP_WAIT1(); else CP_WAIT0();
        __syncthreads();

        float acc1[8][4];
        #pragma unroll
        for (int t = 0; t < 8; t++)
            #pragma unroll
            for (int q = 0; q < 4; q++) acc1[t][q] = 0.f;
        {
            uint32_t bA = sW + (jc & 1)*FW + bOff1;
            #pragma unroll
            for (int ks = 0; ks < 4; ks++) {
                uint32_t a[4];
                LDSM_X4(a, sA + aOff1 + ks*32);
                #pragma unroll
                for (int tq = 0; tq < 4; tq++) {
                    uint32_t q[4];
                    LDSM_X4(q, bA + tq*16*SMPITCH + ks*32);
                    MMA16816(acc1[2*tq],   a, q[0], q[2]);
                    MMA16816(acc1[2*tq+1], a, q[1], q[3]);
                }
            }
        }
        #pragma unroll
        for (int m = 0; m < 8; m++) {
            int jl = wc*64 + (m >> 1)*16 + (m & 1)*8 + ((lane & 3) << 1);
            int j = j0 + jl;
            float b0  = g_b1p[j]   + g_bqk[j];
            float b1v = g_b1p[j+1] + g_bqk[j+1];
            float2 qw = __bfloat1622float2(*(const __nv_bfloat162*)(qWrow + j));
            float2 k0 = __bfloat1622float2(*(const __nv_bfloat162*)(kW0 + j));
            float2 k1 = __bfloat1622float2(*(const __nv_bfloat162*)(kW1 + j));
            float r00 = fmaxf(acc1[m][0] + b0  + qw.x - k0.x, 0.f);
            float r01 = fmaxf(acc1[m][1] + b1v + qw.y - k0.y, 0.f);
            float r10 = fmaxf(acc1[m][2] + b0  + qw.x - k1.x, 0.f);
            float r11 = fmaxf(acc1[m][3] + b1v + qw.y - k1.y, 0.f);
            uint32_t u0, u1;
            asm("cvt.rn.bf16x2.f32 %0, %1, %2;" : "=r"(u0) : "f"(r01), "f"(r00));
            asm("cvt.rn.bf16x2.f32 %0, %1, %2;" : "=r"(u1) : "f"(r11), "f"(r10));
            STS32(hRow0 + jl*2, u0);
            STS32(hRow1 + jl*2, u1);
        }
        __syncthreads();

        {
            uint32_t bA = sB2 + (jc & 1)*FB2 + bOff2;
            #pragma unroll
            for (int ks = 0; ks < 8; ks++) {
                uint32_t a[4];
                LDSM_X4(a, sH + aOff2 + ks*32);
                #pragma unroll
                for (int tp = 0; tp < 8; tp++) {
                    uint32_t q[4];
                    LDSM_X4(q, bA + tp*16*PITCH_H + ks*32);
                    MMA16816(accL[2*tp],   a, q[0], q[2]);
                    MMA16816(accL[2*tp+1], a, q[1], q[3]);
                }
            }
        }
        __syncthreads();
        if (jc + 2 <= 7) FISSUE(jc + 2, jc & 1);
    }
    #undef FISSUE

    const float* peRow = g_PE + ((size_t)b*Pc + ptile + wr*16 + (lane >> 2))*Dc;
    const float* valRow = g_valv + ((size_t)b*Nc + n)*Dc;
    float* aggCol = g_agg + (size_t)b*Dc*Nc + n;

    #pragma unroll
    for (int t = 0; t < 16; t++) {
        int c = wc*128 + t*8 + ((lane & 3) << 1);
        float m0 = fmaxf(accL[t][0], accL[t][2]);
        float m1 = fmaxf(accL[t][1], accL[t][3]);
        #pragma unroll
        for (int d = 4; d <= 16; d <<= 1) {
            m0 = fmaxf(m0, __shfl_xor_sync(0xffffffffu, m0, d));
            m1 = fmaxf(m1, __shfl_xor_sync(0xffffffffu, m1, d));
        }
        float e0 = __expf(accL[t][0] - m0), e2 = __expf(accL[t][2] - m0);
        float e1 = __expf(accL[t][1] - m1), e3 = __expf(accL[t][3] - m1);
        float s0 = e0 + e2, s1 = e1 + e3;
        #pragma unroll
        for (int d = 4; d <= 16; d <<= 1) {
            s0 += __shfl_xor_sync(0xffffffffu, s0, d);
            s1 += __shfl_xor_sync(0xffffffffu, s1, d);
        }
        float2 p0 = *(const float2*)(peRow + c);
        float2 p1 = *(const float2*)(peRow + 8*Dc + c);
        float a0 = e0*p0.x + e2*p1.x;
        float a1 = e1*p0.y + e3*p1.y;
        #pragma unroll
        for (int d = 4; d <= 16; d <<= 1) {
            a0 += __shfl_xor_sync(0xffffffffu, a0, d);
            a1 += __shfl_xor_sync(0xffffffffu, a1, d);
        }
        if (lane < 4) {
            aggCol[(size_t)c*Nc]       = a0/s0 + valRow[c];
            aggCol[(size_t)(c+1)*Nc]   = a1/s1 + valRow[c+1];
        }
    }
}

// ---------------- launch ----------------
extern "C" void kernel_launch(void* const* d_in, const int* in_sizes, int n_in,
                              void* d_out, int out_size)
{
    const float* obj   = (const float*)d_in[0];
    const float* pos   = (const float*)d_in[1];
    const float* qp    = (const float*)d_in[2];
    const float* W_lsq = (const float*)d_in[3];  const float* b_lsq = (const float*)d_in[4];
    const float* W_lso = (const float*)d_in[5];  const float* b_lso = (const float*)d_in[6];
    const float* Wk    = (const float*)d_in[7];  const float* bk    = (const float*)d_in[8];
    const float* Wq    = (const float*)d_in[9];  const float* bq    = (const float*)d_in[10];
    const float* Wv    = (const float*)d_in[11]; const float* bv    = (const float*)d_in[12];
    const float* Wp1   = (const float*)d_in[13]; const float* bp1   = (const float*)d_in[14];
    const float* g1    = (const float*)d_in[15]; const float* bt1   = (const float*)d_in[16];
    const float* m1    = (const float*)d_in[17]; const float* v1    = (const float*)d_in[18];
    const float* Wp2   = (const float*)d_in[19]; const float* bp2   = (const float*)d_in[20];
    const float* Wa1   = (const float*)d_in[21]; const float* ba1   = (const float*)d_in[22];
    const float* g2    = (const float*)d_in[23]; const float* bt2   = (const float*)d_in[24];
    const float* m2    = (const float*)d_in[25]; const float* v2    = (const float*)d_in[26];
    const float* Wa2   = (const float*)d_in[27]; /* ba2 (d_in[28]) cancels in softmax */
    const float* We    = (const float*)d_in[29]; const float* bfin  = (const float*)d_in[30];
    float* out = (float*)d_out;

    cudaFuncSetAttribute(qkw_kernel,       cudaFuncAttributeMaxDynamicSharedMemorySize, SMEM_MMA);
    cudaFuncSetAttribute(mlp_fused_kernel, cudaFuncAttributeMaxDynamicSharedMemorySize, SMEM_FUSED);

    void *pWk, *pWv, *pWq, *pbv, *pval, *pagg, *pWa1f, *pW12h, *pWAQ, *pWAK;
    cudaGetSymbolAddress(&pWk, g_Wk);     cudaGetSymbolAddress(&pWv, g_Wv);
    cudaGetSymbolAddress(&pWq, g_Wq);     cudaGetSymbolAddress(&pbv, g_bv2);
    cudaGetSymbolAddress(&pval, g_valv);  cudaGetSymbolAddress(&pagg, g_agg);
    cudaGetSymbolAddress(&pWa1f, g_Wa1f); cudaGetSymbolAddress(&pW12h, g_W12h);
    cudaGetSymbolAddress(&pWAQ, g_WAQ);   cudaGetSymbolAddress(&pWAK, g_WAK);

    static cudaStream_t s_knn = nullptr;
    static cudaEvent_t  ev_fork = nullptr, ev_fold = nullptr, ev_join = nullptr;
    if (!s_knn) {
        cudaStreamCreateWithFlags(&s_knn, cudaStreamNonBlocking);
        cudaEventCreateWithFlags(&ev_fork, cudaEventDisableTiming);
        cudaEventCreateWithFlags(&ev_fold, cudaEventDisableTiming);
        cudaEventCreateWithFlags(&ev_join, cudaEventDisableTiming);
    }

    // ---- fork: KNN chain (needs only pos) on side stream ----
    cudaEventRecord(ev_fork, 0);
    cudaStreamWaitEvent(s_knn, ev_fork, 0);
    knn_part_kernel<<<dim3(Nc/128, NCH, Bc), 128, 0, s_knn>>>(pos);
    knn_merge_kernel<<<Bc*Nc/256, 256, 0, s_knn>>>();

    // ---- main stream: input transpose + weight prep (tiled) ----
    transpose_in_kernel<<<dim3(Nc/32, Bc*2), 256>>>(qp, obj);
    compose_bias_kernel<<<3, 256>>>(Wk, bk, Wq, bq, Wv, bv, b_lsq, b_lso);
    cgemm_kernel<Dc><<<dim3(CINc/64, Dc/64), 256>>>(Wk, W_lso, (float*)pWk, nullptr, CINc);
    cgemm_kernel<Dc><<<dim3(CINc/64, Dc/64), 256>>>(Wv, W_lso, (float*)pWv, nullptr, CINc);
    cgemm_kernel<Dc><<<dim3(CINc/64, Dc/64), 256>>>(Wq, W_lsq, (float*)pWq, nullptr, CINc);
    fold_kernel<<<1029, 256>>>(Wa1, ba1, g2, bt2, m2, v2, Wp1, bp1, g1, bt1, m1, v1);
    cudaEventRecord(ev_fold, 0);

    // ---- side stream: build (needs g_idx + fold weights) overlaps main GEMMs ----
    cudaStreamWaitEvent(s_knn, ev_fold, 0);
    build_kernel<<<dim3(Nc/4, Bc), 256, 0, s_knn>>>(pos, Wp2, bp2);
    cudaEventRecord(ev_join, s_knn);

    // ---- main stream: composed weights (tiled) + biases + value GEMM + qW/kW ----
    tobf16_kernel<<<1024, 256>>>(Wa2);
    bias2_kernel<<<(2*AHc + 255)/256, 256>>>(bp2);
    cgemm_kernel<Dc><<<dim3(1, AHc/64), 256>>>((const float*)pWa1f, Wp2, nullptr, (__nv_bfloat16*)pW12h, PHc);
    cgemm_kernel<Dc><<<dim3(CINc/64, AHc/64), 256>>>((const float*)pWa1f, (const float*)pWq, nullptr, (__nv_bfloat16*)pWAQ, CINc);
    cgemm_kernel<Dc><<<dim3(CINc/64, AHc/64), 256>>>((const float*)pWa1f, (const float*)pWk, nullptr, (__nv_bfloat16*)pWAK, CINc);
    gemm_kernel<Dc, CINc, true><<<dim3(Nc/64, Dc/64, Bc), 256>>>((const float*)pWv, (const float*)pbv, obj, (float*)pval);
    qkw_kernel<<<dim3(Nc/128, AHc/256, Bc*2), 512, SMEM_MMA>>>();

    // ---- join: fused mlp needs g_hh (build) + g_idx (knn) ----
    cudaStreamWaitEvent(0, ev_join, 0);

    mlp_fused_kernel<<<dim3(Pc/128, 1, Bc), 512, SMEM_FUSED>>>();

    gemm_kernel<CINc, Dc, false><<<dim3(Nc/64, CINc/64, Bc), 256>>>(We, bfin, (const float*)pagg, out);
}

// round 16
// speedup vs baseline: 1.0552x; 1.0552x over previous
#include <cuda_runtime.h>
#include <cuda_bf16.h>
#include <cstdint>

#define Bc   2
#define Nc   4096
#define Kc   16
#define CINc 128
#define Dc   256
#define PHc  64
#define AHc  1024
#define Pc   (Nc*Kc)   /* 65536 */
#define EPSc 1e-5f
#define NCH  8
#define CH   512

typedef unsigned long long ull;

// ---------------- packed f32x2 helpers (used in build) ----------------
__device__ __forceinline__ ull pk2(float a, float b){
    ull r; asm("mov.b64 %0,{%1,%2};" : "=l"(r) : "f"(a), "f"(b)); return r;
}
__device__ __forceinline__ void upk2(ull v, float& a, float& b){
    asm("mov.b64 {%0,%1},%2;" : "=f"(a), "=f"(b) : "l"(v));
}
__device__ __forceinline__ ull fma2(ull a, ull b, ull c){
    ull d; asm("fma.rn.f32x2 %0,%1,%2,%3;" : "=l"(d) : "l"(a), "l"(b), "l"(c)); return d;
}

__device__ __forceinline__ uint32_t smem_u32(const void* p){
    uint32_t a; asm("{ .reg .u64 t; cvta.to.shared.u64 t, %1; cvt.u32.u64 %0, t; }" : "=r"(a) : "l"(p));
    return a;
}

// ---------------- warp-MMA + cp.async helpers ----------------
#define LDSM_X4(r, a) \
    asm volatile("ldmatrix.sync.aligned.m8n8.x4.shared.b16 {%0,%1,%2,%3}, [%4];" \
        : "=r"((r)[0]), "=r"((r)[1]), "=r"((r)[2]), "=r"((r)[3]) : "r"(a))

#define MMA16816(d, a, b0, b1) \
    asm volatile("mma.sync.aligned.m16n8k16.row.col.f32.bf16.bf16.f32 " \
        "{%0,%1,%2,%3},{%4,%5,%6,%7},{%8,%9},{%0,%1,%2,%3};" \
        : "+f"((d)[0]), "+f"((d)[1]), "+f"((d)[2]), "+f"((d)[3]) \
        : "r"((a)[0]), "r"((a)[1]), "r"((a)[2]), "r"((a)[3]), "r"(b0), "r"(b1))

#define CP_ASYNC16(dst, src) \
    asm volatile("cp.async.cg.shared.global [%0], [%1], 16;" :: "r"(dst), "l"(src))
#define CP_COMMIT() asm volatile("cp.async.commit_group;" ::: "memory")
#define CP_WAIT2()  asm volatile("cp.async.wait_group 2;" ::: "memory")
#define CP_WAIT1()  asm volatile("cp.async.wait_group 1;" ::: "memory")
#define CP_WAIT0()  asm volatile("cp.async.wait_group 0;" ::: "memory")
#define STS32(a, v) asm volatile("st.shared.u32 [%0], %1;" :: "r"(a), "r"(v) : "memory")

// ---------------- device scratch ----------------
__device__ float g_Wk[Dc*CINc], g_Wv[Dc*CINc], g_Wq[Dc*CINc];
__device__ float g_bk2[Dc], g_bv2[Dc], g_bq2[Dc];
__device__ float g_Wa1f[AHc*Dc];
__device__ float g_ba1f[AHc];
__device__ float g_Wp1f[PHc*3];
__device__ float g_bp1f[PHc];
__device__ __nv_bfloat16 g_Wa2h[Dc*AHc];   // [c][j] row-major
__device__ __nv_bfloat16 g_W12h[AHc*PHc];  // composed Wa1f@Wp2, [j][t]
__device__ float g_b1p[AHc];               // ba1f + Wa1f@bp2
__device__ __nv_bfloat16 g_WAQ[AHc*CINc];  // Wa1f@Wq_c, [j][c]
__device__ __nv_bfloat16 g_WAK[AHc*CINc];  // Wa1f@Wk_c
__device__ float g_bqk[AHc];               // Wa1f@(bq2-bk2)
__device__ __nv_bfloat16 g_qp_h[Bc*Nc*CINc];   // (b,n,c) bf16 transposed input
__device__ __nv_bfloat16 g_obj_h[Bc*Nc*CINc];
__device__ float g_valv[Bc*Nc*Dc];  // point-major
__device__ __nv_bfloat16 g_qWh[(size_t)Bc*Nc*AHc];  // WAQ·qp per point, bf16
__device__ __nv_bfloat16 g_kWh[(size_t)Bc*Nc*AHc];  // WAK·obj per point, bf16
__device__ int   g_idx[Bc*Nc*Kc];
__device__ float g_pd[(size_t)Bc*NCH*Nc*16];
__device__ int   g_pi[(size_t)Bc*NCH*Nc*16];
__device__ __nv_bfloat16 g_hh[(size_t)Bc*Pc*PHc]; // (b,p,t) relu pos hidden, bf16
__device__ float g_PE[(size_t)Bc*Pc*Dc];          // (b,p,c) fp32: pe
__device__ float g_agg[Bc*Dc*Nc];                 // (b,c,n)

// ---------------- input transpose: (b,c,n) fp32 -> (b,n,c) bf16 ----------------
__global__ void transpose_in_kernel(const float* __restrict__ qp, const float* __restrict__ obj)
{
    __shared__ float t[128][33];
    int z = blockIdx.y; int b = z >> 1; int which = z & 1;
    const float* In = which ? obj : qp;
    __nv_bfloat16* Out = which ? g_obj_h : g_qp_h;
    int n0 = blockIdx.x*32;
    int tid = threadIdx.x;
    int nn = tid & 31, c8 = tid >> 5;
    #pragma unroll
    for (int i = 0; i < 16; i++) {
        int c = c8*16 + i;
        t[c][nn] = In[((size_t)b*CINc + c)*Nc + n0 + nn];
    }
    __syncthreads();
    int c = tid & 127, r2 = tid >> 7;
    #pragma unroll
    for (int i = 0; i < 16; i++) {
        int nr = r2*16 + i;
        Out[((size_t)b*Nc + n0 + nr)*CINc + c] = __float2bfloat16(t[c][nr]);
    }
}

// ---------------- weight composition (one fat launch: 3 GEMMs + biases) ----------------
__global__ void compose_kernel(const float* __restrict__ Wk, const float* __restrict__ bk,
                               const float* __restrict__ Wq, const float* __restrict__ bq,
                               const float* __restrict__ Wv, const float* __restrict__ bv,
                               const float* __restrict__ W_lsq, const float* __restrict__ b_lsq,
                               const float* __restrict__ W_lso, const float* __restrict__ b_lso)
{
    int id = blockIdx.x*256 + threadIdx.x;
    const int total = 3*Dc*CINc;
    if (id < total) {
        int which = id / (Dc*CINc);
        int r = id % (Dc*CINc);
        int o = r / CINc, i = r % CINc;
        const float* A = (which==0) ? Wk : ((which==1) ? Wv : Wq);
        const float* L = (which==2) ? W_lsq : W_lso;
        float s = 0.f;
        #pragma unroll 4
        for (int t = 0; t < Dc; t++) s = fmaf(A[o*Dc+t], L[t*CINc+i], s);
        float* Od = (which==0) ? g_Wk : ((which==1) ? g_Wv : g_Wq);
        Od[o*CINc+i] = s;
    } else if (id < total + 3*Dc) {
        int r = id - total; int which = r / Dc; int o = r % Dc;
        const float* A  = (which==0) ? Wk : ((which==1) ? Wv : Wq);
        const float* bb = (which==0) ? bk : ((which==1) ? bv : bq);
        const float* lb = (which==2) ? b_lsq : b_lso;
        float s = bb[o];
        #pragma unroll 4
        for (int t = 0; t < Dc; t++) s = fmaf(A[o*Dc+t], lb[t], s);
        float* Od = (which==0) ? g_bk2 : ((which==1) ? g_bv2 : g_bq2);
        Od[o] = s;
    }
}

// ---------------- BN folding ----------------
__global__ void fold_kernel(const float* __restrict__ Wa1, const float* __restrict__ ba1,
                            const float* __restrict__ g2,  const float* __restrict__ bt2,
                            const float* __restrict__ m2,  const float* __restrict__ v2,
                            const float* __restrict__ Wp1, const float* __restrict__ bp1,
                            const float* __restrict__ g1,  const float* __restrict__ bt1,
                            const float* __restrict__ m1,  const float* __restrict__ v1)
{
    int id = blockIdx.x*256 + threadIdx.x;
    if (id < AHc*Dc) {
        int j = id / Dc;
        float sc = g2[j] * rsqrtf(v2[j] + EPSc);
        g_Wa1f[id] = sc * Wa1[id];
        return;
    }
    int r = id - AHc*Dc;
    if (r < AHc) {
        float sc = g2[r] * rsqrtf(v2[r] + EPSc);
        g_ba1f[r] = sc*ba1[r] + bt2[r] - m2[r]*sc;
        return;
    }
    r -= AHc;
    if (r < PHc*3) {
        int j = r / 3;
        float sc = g1[j] * rsqrtf(v1[j] + EPSc);
        g_Wp1f[r] = sc * Wp1[r];
        return;
    }
    r -= PHc*3;
    if (r < PHc) {
        float sc = g1[r] * rsqrtf(v1[r] + EPSc);
        g_bp1f[r] = sc*bp1[r] + bt1[r] - m1[r]*sc;
    }
}

// ---------------- compose23: ONE launch for tobf16(Wa2) + W12 + WAQ/WAK + b1p + bqk ----------------
#define C23_T0 (AHc*Dc)               /* tobf16 Wa2 */
#define C23_T1 (C23_T0 + AHc*PHc)     /* W12 */
#define C23_T2 (C23_T1 + 2*AHc*CINc)  /* WAQ/WAK */
#define C23_T3 (C23_T2 + AHc)         /* b1p */
#define C23_T4 (C23_T3 + AHc)         /* bqk */
__global__ void compose23_kernel(const float* __restrict__ Wa2,
                                 const float* __restrict__ Wp2, const float* __restrict__ bp2)
{
    int id = blockIdx.x*256 + threadIdx.x;
    if (id < C23_T0) {
        g_Wa2h[id] = __float2bfloat16(Wa2[id]);
        return;
    }
    if (id < C23_T1) {
        int r = id - C23_T0;
        int j = r >> 6, t = r & 63;
        float s = 0.f;
        #pragma unroll 4
        for (int c = 0; c < Dc; c++) s = fmaf(g_Wa1f[j*Dc + c], Wp2[c*PHc + t], s);
        g_W12h[r] = __float2bfloat16(s);
        return;
    }
    if (id < C23_T2) {
        int r = id - C23_T1;
        int which = r / (AHc*CINc);
        int rr = r % (AHc*CINc);
        int j = rr >> 7, c = rr & 127;
        const float* W = which ? g_Wk : g_Wq;
        float s = 0.f;
        #pragma unroll 4
        for (int t = 0; t < Dc; t++) s = fmaf(g_Wa1f[j*Dc + t], W[t*CINc + c], s);
        (which ? g_WAK : g_WAQ)[rr] = __float2bfloat16(s);
        return;
    }
    if (id < C23_T3) {
        int j = id - C23_T2;
        float s = g_ba1f[j];
        #pragma unroll 4
        for (int c = 0; c < Dc; c++) s = fmaf(g_Wa1f[j*Dc + c], bp2[c], s);
        g_b1p[j] = s;
        return;
    }
    if (id < C23_T4) {
        int j = id - C23_T3;
        float s = 0.f;
        #pragma unroll 4
        for (int t = 0; t < Dc; t++) s = fmaf(g_Wa1f[j*Dc + t], g_bq2[t] - g_bk2[t], s);
        g_bqk[j] = s;
    }
}

// ---------------- KNN part 1 ----------------
__global__ void knn_part_kernel(const float* __restrict__ pos)
{
    __shared__ __align__(16) float4 sc[CH];
    int b = blockIdx.z, ch = blockIdx.y;
    int tid = threadIdx.x;
    int c0 = ch * CH;
    for (int q = tid; q < CH; q += 128) {
        float x = pos[(b*3+0)*Nc + c0 + q];
        float y = pos[(b*3+1)*Nc + c0 + q];
        float z = pos[(b*3+2)*Nc + c0 + q];
        sc[q] = make_float4(x, y, z, fmaf(z, z, fmaf(y, y, x*x)));
    }
    __syncthreads();
    int n = blockIdx.x*128 + tid;
    float qx = pos[(b*3+0)*Nc + n];
    float qy = pos[(b*3+1)*Nc + n];
    float qz = pos[(b*3+2)*Nc + n];
    float qs = fmaf(qz, qz, fmaf(qy, qy, qx*qx));

    float bd[16]; int bi[16];
    #pragma unroll
    for (int t = 0; t < 16; t++) { bd[t] = 3.4e38f; bi[t] = 0; }
    float mx = 3.4e38f; int mp = 0;
    for (int m = 0; m < CH; m++) {
        float4 c = sc[m];
        float dot = fmaf(qz, c.z, fmaf(qy, c.y, qx*c.x));
        float d = (qs + c.w) - 2.0f*dot;
        if (d < mx) {
            bd[mp] = d; bi[mp] = c0 + m;
            mx = bd[0]; mp = 0;
            #pragma unroll
            for (int t = 1; t < 16; t++) if (bd[t] > mx) { mx = bd[t]; mp = t; }
        }
    }
    size_t base = ((size_t)(b*NCH + ch)*Nc + n)*16;
    #pragma unroll
    for (int t = 0; t < 16; t++) { g_pd[base + t] = bd[t]; g_pi[base + t] = bi[t]; }
}

// ---------------- KNN part 2: merge ----------------
__global__ void knn_merge_kernel()
{
    int id = blockIdx.x*256 + threadIdx.x;
    int b = id >> 12, n = id & (Nc-1);
    float bd[16]; int bi[16];
    #pragma unroll
    for (int t = 0; t < 16; t++) { bd[t] = 3.4e38f; bi[t] = 0; }
    float mx = 3.4e38f; int mp = 0;
    for (int ch = 0; ch < NCH; ch++) {
        size_t base = ((size_t)(b*NCH + ch)*Nc + n)*16;
        #pragma unroll
        for (int t = 0; t < 16; t++) {
            float d = g_pd[base + t];
            if (d < mx) {
                bd[mp] = d; bi[mp] = g_pi[base + t];
                mx = bd[0]; mp = 0;
                #pragma unroll
                for (int u = 1; u < 16; u++) if (bd[u] > mx) { mx = bd[u]; mp = u; }
            }
        }
    }
    #pragma unroll
    for (int t = 0; t < 16; t++) g_idx[(b*Nc+n)*16 + t] = bi[t];
}

// ---------------- tiled fp32 GEMM (value conv + final conv) ----------------
template<int O, int I, bool POINT_MAJOR>
__global__ void gemm_kernel(const float* __restrict__ W, const float* __restrict__ bias,
                            const float* __restrict__ In, float* __restrict__ Out)
{
    __shared__ float Wt[64][33];
    __shared__ float Xt[32][64];
    int b  = blockIdx.z;
    int n0 = blockIdx.x*64, o0 = blockIdx.y*64;
    int tid = threadIdx.x, tx = tid & 15, ty = tid >> 4;
    float acc[4][4];
    #pragma unroll
    for (int r = 0; r < 4; r++)
        #pragma unroll
        for (int c = 0; c < 4; c++) acc[r][c] = 0.f;

    for (int k0 = 0; k0 < I; k0 += 32) {
        for (int q = tid; q < 64*32; q += 256) {
            int oo = q >> 5, kk = q & 31;
            Wt[oo][kk] = W[(o0+oo)*I + k0 + kk];
        }
        for (int q = tid; q < 32*64; q += 256) {
            int kk = q >> 6, nn = q & 63;
            Xt[kk][nn] = In[((size_t)b*I + k0 + kk)*Nc + n0 + nn];
        }
        __syncthreads();
        #pragma unroll 8
        for (int kk = 0; kk < 32; kk++) {
            float a[4], bb[4];
            #pragma unroll
            for (int r = 0; r < 4; r++) a[r]  = Wt[ty*4+r][kk];
            #pragma unroll
            for (int c = 0; c < 4; c++) bb[c] = Xt[kk][tx*4+c];
            #pragma unroll
            for (int r = 0; r < 4; r++)
                #pragma unroll
                for (int c = 0; c < 4; c++) acc[r][c] = fmaf(a[r], bb[c], acc[r][c]);
        }
        __syncthreads();
    }
    #pragma unroll
    for (int r = 0; r < 4; r++) {
        float bv = bias[o0 + ty*4 + r];
        #pragma unroll
        for (int c = 0; c < 4; c++) {
            float v = acc[r][c] + bv;
            int oo = o0 + ty*4 + r, nn = n0 + tx*4 + c;
            if (POINT_MAJOR)
                Out[((size_t)b*Nc + nn)*O + oo] = v;
            else
                Out[((size_t)b*O + oo)*Nc + nn] = v;
        }
    }
}

// ---------------- build: pos-MLP hidden h (bf16) + PE (fp32) ----------------
__global__ void build_kernel(const float* __restrict__ pos,
                             const float* __restrict__ Wp2,
                             const float* __restrict__ bp2)
{
    __shared__ float pr[3][64];
    __shared__ __align__(16) float sh[PHc*64];
    __shared__ int sidx[64];
    int b = blockIdx.y;
    int nbase = blockIdx.x*4;
    int pbase = nbase*16;
    int tid = threadIdx.x;

    if (tid < 64) sidx[tid] = g_idx[(b*Nc + nbase)*16 + tid];
    __syncthreads();
    if (tid < 192) {
        int d = tid >> 6, pp = tid & 63;
        int n  = nbase + (pp >> 4);
        int nb = sidx[pp];
        pr[d][pp] = pos[(b*3+d)*Nc + n] - pos[(b*3+d)*Nc + nb];
    }
    __syncthreads();
    for (int q = tid; q < PHc*64; q += 256) {
        int j = q >> 6, pp = q & 63;
        float h = fmaf(g_Wp1f[j*3+2], pr[2][pp],
                  fmaf(g_Wp1f[j*3+1], pr[1][pp],
                  fmaf(g_Wp1f[j*3+0], pr[0][pp], g_bp1f[j])));
        sh[q] = fmaxf(h, 0.f);
    }
    __syncthreads();

    for (int q = tid; q < PHc*64; q += 256) {
        int pp = q >> 6, j = q & 63;
        g_hh[((size_t)b*Pc + pbase + pp)*PHc + j] = __float2bfloat16(sh[j*64 + pp]);
    }

    int c = tid;
    float bc = bp2[c];
    ull A[32];
    #pragma unroll
    for (int g = 0; g < 32; g++) A[g] = pk2(bc, bc);
    const ull* HP = (const ull*)sh;
    #pragma unroll 2
    for (int j = 0; j < PHc; j++) {
        float w = Wp2[c*PHc + j];
        ull wb = pk2(w, w);
        const ull* hp = HP + j*32;
        #pragma unroll
        for (int g = 0; g < 32; g++) A[g] = fma2(wb, hp[g], A[g]);
    }
    #pragma unroll
    for (int g = 0; g < 32; g++) {
        float p0, p1; upk2(A[g], p0, p1);
        g_PE[((size_t)b*Pc + pbase + g*2)*Dc + c]     = p0;
        g_PE[((size_t)b*Pc + pbase + g*2 + 1)*Dc + c] = p1;
    }
}

// ---------------- warp-MMA core with 3-stage cp.async pipeline (qkw) ----------------
#define SMPITCH 144
#define ABUF (128*SMPITCH)
#define BBUF (256*SMPITCH)
#define SMEM_MMA (3*(ABUF+BBUF))   /* 165888 B */

template<int KTOT>
__device__ __forceinline__ void mma_core(char* sm,
                                         const __nv_bfloat16* __restrict__ gA,
                                         const __nv_bfloat16* __restrict__ gB,
                                         float (&acc)[16][4])
{
    uint32_t sA = smem_u32(sm);
    uint32_t sB = sA + 3*ABUF;
    int tid = threadIdx.x;
    int lane = tid & 31, wid = tid >> 5;
    int wr = wid >> 1, wc = wid & 1;

    uint32_t aOff = (uint32_t)(wr*16 + (lane & 15))*SMPITCH + (uint32_t)((lane >> 4) << 4);
    uint32_t bOff = (uint32_t)(wc*128 + (lane & 15))*SMPITCH + (uint32_t)((lane >> 4) << 4);

    const int NS = KTOT/64;
    int arow = tid >> 3, ac8 = (tid & 7) << 3;
    #define MMA_ISSUE(s, buf) do { \
        uint32_t dA = sA + (buf)*ABUF; \
        uint32_t dB = sB + (buf)*BBUF; \
        _Pragma("unroll") \
        for (int it = 0; it < 2; it++) { \
            int row = arow + it*64; \
            CP_ASYNC16(dA + row*SMPITCH + ac8*2, gA + (size_t)row*KTOT + (s)*64 + ac8); \
        } \
        _Pragma("unroll") \
        for (int it = 0; it < 4; it++) { \
            int row = arow + it*64; \
            CP_ASYNC16(dB + row*SMPITCH + ac8*2, gB + (size_t)row*KTOT + (s)*64 + ac8); \
        } \
        CP_COMMIT(); \
    } while(0)

    MMA_ISSUE(0, 0);
    if (NS > 1) MMA_ISSUE(1, 1);
    int buf = 0;
    for (int i = 0; i < NS; i++) {
        if (i + 2 < NS)      { MMA_ISSUE(i+2, (buf+2 >= 3) ? buf-1 : buf+2); CP_WAIT2(); }
        else if (i + 1 < NS) { CP_WAIT1(); }
        else                 { CP_WAIT0(); }
        __syncthreads();
        uint32_t aAddr = sA + buf*ABUF + aOff;
        uint32_t bAddr = sB + buf*BBUF + bOff;
        #pragma unroll
        for (int ks = 0; ks < 4; ks++) {
            uint32_t a[4];
            LDSM_X4(a, aAddr + ks*32);
            #pragma unroll
            for (int tp = 0; tp < 8; tp++) {
                uint32_t q[4];
                LDSM_X4(q, bAddr + tp*16*SMPITCH + ks*32);
                MMA16816(acc[2*tp],   a, q[0], q[2]);
                MMA16816(acc[2*tp+1], a, q[1], q[3]);
            }
        }
        __syncthreads();
        buf = (buf + 1 >= 3) ? 0 : buf + 1;
    }
    #undef MMA_ISSUE
}

// ---------------- qkw: qW = WAQ·qp, kW = WAK·obj per point (K=128), bf16 out ----------------
__global__ void __launch_bounds__(512, 1) qkw_kernel()
{
    extern __shared__ __align__(16) char smq[];
    int z = blockIdx.z;
    int b = z >> 1, which = z & 1;
    int ntile = blockIdx.x*128;
    int j0 = blockIdx.y*256;
    const __nv_bfloat16* gA = (which ? g_qp_h : g_obj_h) + ((size_t)b*Nc + ntile)*CINc;
    const __nv_bfloat16* gB = (which ? g_WAQ : g_WAK) + (size_t)j0*CINc;
    __nv_bfloat16* Out = (which ? g_qWh : g_kWh) + ((size_t)b*Nc)*AHc;

    float acc[16][4];
    #pragma unroll
    for (int t = 0; t < 16; t++)
        #pragma unroll
        for (int q = 0; q < 4; q++) acc[t][q] = 0.f;

    mma_core<CINc>(smq, gA, gB, acc);

    int tid = threadIdx.x, lane = tid & 31, wid = tid >> 5;
    int wr = wid >> 1, wc = wid & 1;
    int row0 = ntile + wr*16 + (lane >> 2);
    __nv_bfloat16* O0 = Out + (size_t)row0*AHc + j0;
    __nv_bfloat16* O1 = O0 + (size_t)8*AHc;
    #pragma unroll
    for (int t = 0; t < 16; t++) {
        int c = wc*128 + t*8 + ((lane & 3) << 1);
        uint32_t u0, u1;
        asm("cvt.rn.bf16x2.f32 %0, %1, %2;" : "=r"(u0) : "f"(acc[t][1]), "f"(acc[t][0]));
        asm("cvt.rn.bf16x2.f32 %0, %1, %2;" : "=r"(u1) : "f"(acc[t][3]), "f"(acc[t][2]));
        *(uint32_t*)(O0 + c) = u0;
        *(uint32_t*)(O1 + c) = u1;
    }
}

// ---------------- FUSED mlp ----------------
#define PITCH_H 272                 /* 128 bf16 + 8 pad */
#define FA  (128*SMPITCH)
#define FW  (128*SMPITCH)
#define FH  (128*PITCH_H)
#define FB2 (256*PITCH_H)
#define SMEM_FUSED (FA + 2*FW + FH + 2*FB2)   /* 229376 B */

__global__ void __launch_bounds__(512, 1) mlp_fused_kernel()
{
    extern __shared__ __align__(16) char smf[];
    int b = blockIdx.z;
    int ptile = blockIdx.x*128;
    const __nv_bfloat16* gA = g_hh + ((size_t)b*Pc + ptile)*PHc;

    uint32_t sA  = smem_u32(smf);
    uint32_t sW  = sA + FA;
    uint32_t sH  = sW + 2*FW;
    uint32_t sB2 = sH + FH;
    int tid = threadIdx.x;
    int lane = tid & 31, wid = tid >> 5;
    int wr = wid >> 1, wc = wid & 1;

    #define FISSUE(jc_, buf_) do { \
        uint32_t dW = sW + (buf_)*FW; \
        uint32_t dB = sB2 + (buf_)*FB2; \
        int j0_ = (jc_)*128; \
        _Pragma("unroll") \
        for (int it = 0; it < 2; it++) { \
            int u = tid + it*512; int row = u >> 3, c8 = (u & 7) << 3; \
            CP_ASYNC16(dW + row*SMPITCH + c8*2, g_W12h + (size_t)(j0_ + row)*PHc + c8); \
        } \
        _Pragma("unroll") \
        for (int it = 0; it < 8; it++) { \
            int u = tid + it*512; int row = u >> 4, c8 = (u & 15) << 3; \
            CP_ASYNC16(dB + row*PITCH_H + c8*2, g_Wa2h + (size_t)row*AHc + j0_ + c8); \
        } \
        CP_COMMIT(); \
    } while(0)

    {
        #pragma unroll
        for (int it = 0; it < 2; it++) {
            int u = tid + it*512; int row = u >> 3, c8 = (u & 7) << 3;
            CP_ASYNC16(sA + row*SMPITCH + c8*2, gA + (size_t)row*PHc + c8);
        }
    }
    FISSUE(0, 0);
    FISSUE(1, 1);

    float accL[16][4];
    #pragma unroll
    for (int t = 0; t < 16; t++)
        #pragma unroll
        for (int q = 0; q < 4; q++) accL[t][q] = 0.f;

    int n = (ptile >> 4) + wr;
    int k0i = lane >> 2;
    int nb0 = g_idx[(b*Nc + n)*16 + k0i];
    int nb1 = g_idx[(b*Nc + n)*16 + k0i + 8];
    const __nv_bfloat16* qWrow = g_qWh + ((size_t)b*Nc + n)*AHc;
    const __nv_bfloat16* kW0   = g_kWh + ((size_t)b*Nc + nb0)*AHc;
    const __nv_bfloat16* kW1   = g_kWh + ((size_t)b*Nc + nb1)*AHc;

    uint32_t aOff1 = (uint32_t)(wr*16 + (lane & 15))*SMPITCH + (uint32_t)((lane >> 4) << 4);
    uint32_t bOff1 = (uint32_t)(wc*64 + (lane & 15))*SMPITCH + (uint32_t)((lane >> 4) << 4);
    uint32_t aOff2 = (uint32_t)(wr*16 + (lane & 15))*PITCH_H + (uint32_t)((lane >> 4) << 4);
    uint32_t bOff2 = (uint32_t)(wc*128 + (lane & 15))*PITCH_H + (uint32_t)((lane >> 4) << 4);
    uint32_t hRow0 = sH + (uint32_t)(wr*16 + (lane >> 2))*PITCH_H;
    uint32_t hRow1 = hRow0 + 8*PITCH_H;

    for (int jc = 0; jc < 8; jc++) {
        int j0 = jc*128;
        if (jc < 7) CP_WAIT1(); else CP_WAIT0();
        __syncthreads();

        float acc1[8][4];
        #pragma unroll
        for (int t = 0; t < 8; t++)
            #pragma unroll
            for (int q = 0; q < 4; q++) acc1[t][q] = 0.f;
        {
            uint32_t bA = sW + (jc & 1)*FW + bOff1;
            #pragma unroll
            for (int ks = 0; ks < 4; ks++) {
                uint32_t a[4];
                LDSM_X4(a, sA + aOff1 + ks*32);
                #pragma unroll
                for (int tq = 0; tq < 4; tq++) {
                    uint32_t q[4];
                    LDSM_X4(q, bA + tq*16*SMPITCH + ks*32);
                    MMA16816(acc1[2*tq],   a, q[0], q[2]);
                    MMA16816(acc1[2*tq+1], a, q[1], q[3]);
                }
            }
        }
        #pragma unroll
        for (int m = 0; m < 8; m++) {
            int jl = wc*64 + (m >> 1)*16 + (m & 1)*8 + ((lane & 3) << 1);
            int j = j0 + jl;
            float b0  = g_b1p[j]   + g_bqk[j];
            float b1v = g_b1p[j+1] + g_bqk[j+1];
            float2 qw = __bfloat1622float2(*(const __nv_bfloat162*)(qWrow + j));
            float2 k0 = __bfloat1622float2(*(const __nv_bfloat162*)(kW0 + j));
            float2 k1 = __bfloat1622float2(*(const __nv_bfloat162*)(kW1 + j));
            float r00 = fmaxf(acc1[m][0] + b0  + qw.x - k0.x, 0.f);
            float r01 = fmaxf(acc1[m][1] + b1v + qw.y - k0.y, 0.f);
            float r10 = fmaxf(acc1[m][2] + b0  + qw.x - k1.x, 0.f);
            float r11 = fmaxf(acc1[m][3] + b1v + qw.y - k1.y, 0.f);
            uint32_t u0, u1;
            asm("cvt.rn.bf16x2.f32 %0, %1, %2;" : "=r"(u0) : "f"(r01), "f"(r00));
            asm("cvt.rn.bf16x2.f32 %0, %1, %2;" : "=r"(u1) : "f"(r11), "f"(r10));
            STS32(hRow0 + jl*2, u0);
            STS32(hRow1 + jl*2, u1);
        }
        __syncthreads();

        {
            uint32_t bA = sB2 + (jc & 1)*FB2 + bOff2;
            #pragma unroll
            for (int ks = 0; ks < 8; ks++) {
                uint32_t a[4];
                LDSM_X4(a, sH + aOff2 + ks*32);
                #pragma unroll
                for (int tp = 0; tp < 8; tp++) {
                    uint32_t q[4];
                    LDSM_X4(q, bA + tp*16*PITCH_H + ks*32);
                    MMA16816(accL[2*tp],   a, q[0], q[2]);
                    MMA16816(accL[2*tp+1], a, q[1], q[3]);
                }
            }
        }
        __syncthreads();
        if (jc + 2 <= 7) FISSUE(jc + 2, jc & 1);
    }
    #undef FISSUE

    const float* peRow = g_PE + ((size_t)b*Pc + ptile + wr*16 + (lane >> 2))*Dc;
    const float* valRow = g_valv + ((size_t)b*Nc + n)*Dc;
    float* aggCol = g_agg + (size_t)b*Dc*Nc + n;

    #pragma unroll
    for (int t = 0; t < 16; t++) {
        int c = wc*128 + t*8 + ((lane & 3) << 1);
        float m0 = fmaxf(accL[t][0], accL[t][2]);
        float m1 = fmaxf(accL[t][1], accL[t][3]);
        #pragma unroll
        for (int d = 4; d <= 16; d <<= 1) {
            m0 = fmaxf(m0, __shfl_xor_sync(0xffffffffu, m0, d));
            m1 = fmaxf(m1, __shfl_xor_sync(0xffffffffu, m1, d));
        }
        float e0 = __expf(accL[t][0] - m0), e2 = __expf(accL[t][2] - m0);
        float e1 = __expf(accL[t][1] - m1), e3 = __expf(accL[t][3] - m1);
        float s0 = e0 + e2, s1 = e1 + e3;
        #pragma unroll
        for (int d = 4; d <= 16; d <<= 1) {
            s0 += __shfl_xor_sync(0xffffffffu, s0, d);
            s1 += __shfl_xor_sync(0xffffffffu, s1, d);
        }
        float2 p0 = *(const float2*)(peRow + c);
        float2 p1 = *(const float2*)(peRow + 8*Dc + c);
        float a0 = e0*p0.x + e2*p1.x;
        float a1 = e1*p0.y + e3*p1.y;
        #pragma unroll
        for (int d = 4; d <= 16; d <<= 1) {
            a0 += __shfl_xor_sync(0xffffffffu, a0, d);
            a1 += __shfl_xor_sync(0xffffffffu, a1, d);
        }
        if (lane < 4) {
            aggCol[(size_t)c*Nc]       = a0/s0 + valRow[c];
            aggCol[(size_t)(c+1)*Nc]   = a1/s1 + valRow[c+1];
        }
    }
}

// ---------------- launch ----------------
extern "C" void kernel_launch(void* const* d_in, const int* in_sizes, int n_in,
                              void* d_out, int out_size)
{
    const float* obj   = (const float*)d_in[0];
    const float* pos   = (const float*)d_in[1];
    const float* qp    = (const float*)d_in[2];
    const float* W_lsq = (const float*)d_in[3];  const float* b_lsq = (const float*)d_in[4];
    const float* W_lso = (const float*)d_in[5];  const float* b_lso = (const float*)d_in[6];
    const float* Wk    = (const float*)d_in[7];  const float* bk    = (const float*)d_in[8];
    const float* Wq    = (const float*)d_in[9];  const float* bq    = (const float*)d_in[10];
    const float* Wv    = (const float*)d_in[11]; const float* bv    = (const float*)d_in[12];
    const float* Wp1   = (const float*)d_in[13]; const float* bp1   = (const float*)d_in[14];
    const float* g1    = (const float*)d_in[15]; const float* bt1   = (const float*)d_in[16];
    const float* m1    = (const float*)d_in[17]; const float* v1    = (const float*)d_in[18];
    const float* Wp2   = (const float*)d_in[19]; const float* bp2   = (const float*)d_in[20];
    const float* Wa1   = (const float*)d_in[21]; const float* ba1   = (const float*)d_in[22];
    const float* g2    = (const float*)d_in[23]; const float* bt2   = (const float*)d_in[24];
    const float* m2    = (const float*)d_in[25]; const float* v2    = (const float*)d_in[26];
    const float* Wa2   = (const float*)d_in[27]; /* ba2 (d_in[28]) cancels in softmax */
    const float* We    = (const float*)d_in[29]; const float* bfin  = (const float*)d_in[30];
    float* out = (float*)d_out;

    cudaFuncSetAttribute(qkw_kernel,       cudaFuncAttributeMaxDynamicSharedMemorySize, SMEM_MMA);
    cudaFuncSetAttribute(mlp_fused_kernel, cudaFuncAttributeMaxDynamicSharedMemorySize, SMEM_FUSED);

    void *pWv, *pbv, *pval, *pagg;
    cudaGetSymbolAddress(&pWv, g_Wv);   cudaGetSymbolAddress(&pbv, g_bv2);
    cudaGetSymbolAddress(&pval, g_valv); cudaGetSymbolAddress(&pagg, g_agg);

    static cudaStream_t s_knn = nullptr, s_val = nullptr;
    static cudaEvent_t  ev_fork = nullptr, ev_fold = nullptr, ev_join = nullptr;
    static cudaEvent_t  ev_comp = nullptr, ev_val = nullptr;
    if (!s_knn) {
        cudaStreamCreateWithFlags(&s_knn, cudaStreamNonBlocking);
        cudaStreamCreateWithFlags(&s_val, cudaStreamNonBlocking);
        cudaEventCreateWithFlags(&ev_fork, cudaEventDisableTiming);
        cudaEventCreateWithFlags(&ev_fold, cudaEventDisableTiming);
        cudaEventCreateWithFlags(&ev_join, cudaEventDisableTiming);
        cudaEventCreateWithFlags(&ev_comp, cudaEventDisableTiming);
        cudaEventCreateWithFlags(&ev_val,  cudaEventDisableTiming);
    }

    // ---- fork: KNN chain (needs only pos) on side stream ----
    cudaEventRecord(ev_fork, 0);
    cudaStreamWaitEvent(s_knn, ev_fork, 0);
    knn_part_kernel<<<dim3(Nc/128, NCH, Bc), 128, 0, s_knn>>>(pos);
    knn_merge_kernel<<<Bc*Nc/256, 256, 0, s_knn>>>();

    // ---- main stream: input transpose + fused compose (3 GEMMs + biases) ----
    transpose_in_kernel<<<dim3(Nc/32, Bc*2), 256>>>(qp, obj);
    compose_kernel<<<387, 256>>>(Wk, bk, Wq, bq, Wv, bv, W_lsq, b_lsq, W_lso, b_lso);
    cudaEventRecord(ev_comp, 0);

    // ---- value stream: value GEMM (needs g_Wv/g_bv2 only) overlaps fold/compose23/qkw ----
    cudaStreamWaitEvent(s_val, ev_comp, 0);
    gemm_kernel<Dc, CINc, true><<<dim3(Nc/64, Dc/64, Bc), 256, 0, s_val>>>((const float*)pWv, (const float*)pbv, obj, (float*)pval);
    cudaEventRecord(ev_val, s_val);

    // ---- main stream: fold + merged compose23 + qkw ----
    fold_kernel<<<1029, 256>>>(Wa1, ba1, g2, bt2, m2, v2, Wp1, bp1, g1, bt1, m1, v1);
    cudaEventRecord(ev_fold, 0);

    // ---- side stream: build (needs g_idx + fold weights) overlaps main GEMMs ----
    cudaStreamWaitEvent(s_knn, ev_fold, 0);
    build_kernel<<<dim3(Nc/4, Bc), 256, 0, s_knn>>>(pos, Wp2, bp2);
    cudaEventRecord(ev_join, s_knn);

    compose23_kernel<<<(C23_T4 + 255)/256, 256>>>(Wa2, Wp2, bp2);
    qkw_kernel<<<dim3(Nc/128, AHc/256, Bc*2), 512, SMEM_MMA>>>();

    // ---- join: fused mlp needs g_hh (build) + g_idx (knn) + g_valv (value stream) ----
    cudaStreamWaitEvent(0, ev_join, 0);
    cudaStreamWaitEvent(0, ev_val, 0);

    mlp_fused_kernel<<<dim3(Pc/128, 1, Bc), 512, SMEM_FUSED>>>();

    gemm_kernel<CINc, Dc, false><<<dim3(Nc/64, CINc/64, Bc), 256>>>(We, bfin, (const float*)pagg, out);
}

// round 17
// speedup vs baseline: 1.1129x; 1.0547x over previous
#include <cuda_runtime.h>
#include <cuda_bf16.h>
#include <cstdint>

#define Bc   2
#define Nc   4096
#define Kc   16
#define CINc 128
#define Dc   256
#define PHc  64
#define AHc  1024
#define Pc   (Nc*Kc)   /* 65536 */
#define EPSc 1e-5f
#define NCH  8
#define CH   512

typedef unsigned long long ull;

// ---------------- packed f32x2 helpers (used in build) ----------------
__device__ __forceinline__ ull pk2(float a, float b){
    ull r; asm("mov.b64 %0,{%1,%2};" : "=l"(r) : "f"(a), "f"(b)); return r;
}
__device__ __forceinline__ void upk2(ull v, float& a, float& b){
    asm("mov.b64 {%0,%1},%2;" : "=f"(a), "=f"(b) : "l"(v));
}
__device__ __forceinline__ ull fma2(ull a, ull b, ull c){
    ull d; asm("fma.rn.f32x2 %0,%1,%2,%3;" : "=l"(d) : "l"(a), "l"(b), "l"(c)); return d;
}

__device__ __forceinline__ uint32_t smem_u32(const void* p){
    uint32_t a; asm("{ .reg .u64 t; cvta.to.shared.u64 t, %1; cvt.u32.u64 %0, t; }" : "=r"(a) : "l"(p));
    return a;
}

// ---------------- warp-MMA + cp.async helpers ----------------
#define LDSM_X4(r, a) \
    asm volatile("ldmatrix.sync.aligned.m8n8.x4.shared.b16 {%0,%1,%2,%3}, [%4];" \
        : "=r"((r)[0]), "=r"((r)[1]), "=r"((r)[2]), "=r"((r)[3]) : "r"(a))

#define MMA16816(d, a, b0, b1) \
    asm volatile("mma.sync.aligned.m16n8k16.row.col.f32.bf16.bf16.f32 " \
        "{%0,%1,%2,%3},{%4,%5,%6,%7},{%8,%9},{%0,%1,%2,%3};" \
        : "+f"((d)[0]), "+f"((d)[1]), "+f"((d)[2]), "+f"((d)[3]) \
        : "r"((a)[0]), "r"((a)[1]), "r"((a)[2]), "r"((a)[3]), "r"(b0), "r"(b1))

#define CP_ASYNC16(dst, src) \
    asm volatile("cp.async.cg.shared.global [%0], [%1], 16;" :: "r"(dst), "l"(src))
#define CP_COMMIT() asm volatile("cp.async.commit_group;" ::: "memory")
#define CP_WAIT2()  asm volatile("cp.async.wait_group 2;" ::: "memory")
#define CP_WAIT1()  asm volatile("cp.async.wait_group 1;" ::: "memory")
#define CP_WAIT0()  asm volatile("cp.async.wait_group 0;" ::: "memory")
#define STS32(a, v) asm volatile("st.shared.u32 [%0], %1;" :: "r"(a), "r"(v) : "memory")

// ---------------- device scratch ----------------
__device__ float g_Wk[Dc*CINc], g_Wv[Dc*CINc], g_Wq[Dc*CINc];
__device__ float g_bk2[Dc], g_bv2[Dc], g_bq2[Dc];
__device__ float g_Wa1f[AHc*Dc];
__device__ float g_ba1f[AHc];
__device__ float g_Wp1f[PHc*3];
__device__ float g_bp1f[PHc];
__device__ __nv_bfloat16 g_Wa2h[Dc*AHc];   // [c][j] row-major
__device__ __nv_bfloat16 g_W12h[AHc*PHc];  // composed Wa1f@Wp2, [j][t]
__device__ float g_b1p[AHc];               // ba1f + Wa1f@bp2
__device__ __nv_bfloat16 g_WAQ[AHc*CINc];  // Wa1f@Wq_c, [j][c]
__device__ __nv_bfloat16 g_WAK[AHc*CINc];  // Wa1f@Wk_c
__device__ float g_bqk[AHc];               // Wa1f@(bq2-bk2)
__device__ __nv_bfloat16 g_qp_h[Bc*Nc*CINc];   // (b,n,c) bf16 transposed input
__device__ __nv_bfloat16 g_obj_h[Bc*Nc*CINc];
__device__ float g_valv[Bc*Nc*Dc];  // point-major
__device__ __nv_bfloat16 g_qWh[(size_t)Bc*Nc*AHc];  // WAQ·qp + b1p + bqk, bf16
__device__ __nv_bfloat16 g_kWh[(size_t)Bc*Nc*AHc];  // WAK·obj per point, bf16
__device__ int   g_idx[Bc*Nc*Kc];
__device__ float g_pd[(size_t)Bc*NCH*Nc*16];
__device__ int   g_pi[(size_t)Bc*NCH*Nc*16];
__device__ __nv_bfloat16 g_hh[(size_t)Bc*Pc*PHc]; // (b,p,t) relu pos hidden, bf16
__device__ float g_PE[(size_t)Bc*Pc*Dc];          // (b,p,c) fp32: pe
__device__ float g_agg[(size_t)Bc*Nc*Dc];         // POINT-major (b,n,c)

// ---------------- input transpose: (b,c,n) fp32 -> (b,n,c) bf16 ----------------
__global__ void transpose_in_kernel(const float* __restrict__ qp, const float* __restrict__ obj)
{
    __shared__ float t[128][33];
    int z = blockIdx.y; int b = z >> 1; int which = z & 1;
    const float* In = which ? obj : qp;
    __nv_bfloat16* Out = which ? g_obj_h : g_qp_h;
    int n0 = blockIdx.x*32;
    int tid = threadIdx.x;
    int nn = tid & 31, c8 = tid >> 5;
    #pragma unroll
    for (int i = 0; i < 16; i++) {
        int c = c8*16 + i;
        t[c][nn] = In[((size_t)b*CINc + c)*Nc + n0 + nn];
    }
    __syncthreads();
    int c = tid & 127, r2 = tid >> 7;
    #pragma unroll
    for (int i = 0; i < 16; i++) {
        int nr = r2*16 + i;
        Out[((size_t)b*Nc + n0 + nr)*CINc + c] = __float2bfloat16(t[c][nr]);
    }
}

// ---------------- weight composition (one fat launch: 3 GEMMs + biases) ----------------
__global__ void compose_kernel(const float* __restrict__ Wk, const float* __restrict__ bk,
                               const float* __restrict__ Wq, const float* __restrict__ bq,
                               const float* __restrict__ Wv, const float* __restrict__ bv,
                               const float* __restrict__ W_lsq, const float* __restrict__ b_lsq,
                               const float* __restrict__ W_lso, const float* __restrict__ b_lso)
{
    int id = blockIdx.x*256 + threadIdx.x;
    const int total = 3*Dc*CINc;
    if (id < total) {
        int which = id / (Dc*CINc);
        int r = id % (Dc*CINc);
        int o = r / CINc, i = r % CINc;
        const float* A = (which==0) ? Wk : ((which==1) ? Wv : Wq);
        const float* L = (which==2) ? W_lsq : W_lso;
        float s = 0.f;
        #pragma unroll 4
        for (int t = 0; t < Dc; t++) s = fmaf(A[o*Dc+t], L[t*CINc+i], s);
        float* Od = (which==0) ? g_Wk : ((which==1) ? g_Wv : g_Wq);
        Od[o*CINc+i] = s;
    } else if (id < total + 3*Dc) {
        int r = id - total; int which = r / Dc; int o = r % Dc;
        const float* A  = (which==0) ? Wk : ((which==1) ? Wv : Wq);
        const float* bb = (which==0) ? bk : ((which==1) ? bv : bq);
        const float* lb = (which==2) ? b_lsq : b_lso;
        float s = bb[o];
        #pragma unroll 4
        for (int t = 0; t < Dc; t++) s = fmaf(A[o*Dc+t], lb[t], s);
        float* Od = (which==0) ? g_bk2 : ((which==1) ? g_bv2 : g_bq2);
        Od[o] = s;
    }
}

// ---------------- BN folding ----------------
__global__ void fold_kernel(const float* __restrict__ Wa1, const float* __restrict__ ba1,
                            const float* __restrict__ g2,  const float* __restrict__ bt2,
                            const float* __restrict__ m2,  const float* __restrict__ v2,
                            const float* __restrict__ Wp1, const float* __restrict__ bp1,
                            const float* __restrict__ g1,  const float* __restrict__ bt1,
                            const float* __restrict__ m1,  const float* __restrict__ v1)
{
    int id = blockIdx.x*256 + threadIdx.x;
    if (id < AHc*Dc) {
        int j = id / Dc;
        float sc = g2[j] * rsqrtf(v2[j] + EPSc);
        g_Wa1f[id] = sc * Wa1[id];
        return;
    }
    int r = id - AHc*Dc;
    if (r < AHc) {
        float sc = g2[r] * rsqrtf(v2[r] + EPSc);
        g_ba1f[r] = sc*ba1[r] + bt2[r] - m2[r]*sc;
        return;
    }
    r -= AHc;
    if (r < PHc*3) {
        int j = r / 3;
        float sc = g1[j] * rsqrtf(v1[j] + EPSc);
        g_Wp1f[r] = sc * Wp1[r];
        return;
    }
    r -= PHc*3;
    if (r < PHc) {
        float sc = g1[r] * rsqrtf(v1[r] + EPSc);
        g_bp1f[r] = sc*bp1[r] + bt1[r] - m1[r]*sc;
    }
}

// ---------------- compose23: ONE launch for tobf16(Wa2) + W12 + WAQ/WAK + b1p + bqk ----------------
#define C23_T0 (AHc*Dc)               /* tobf16 Wa2 */
#define C23_T1 (C23_T0 + AHc*PHc)     /* W12 */
#define C23_T2 (C23_T1 + 2*AHc*CINc)  /* WAQ/WAK */
#define C23_T3 (C23_T2 + AHc)         /* b1p */
#define C23_T4 (C23_T3 + AHc)         /* bqk */
__global__ void compose23_kernel(const float* __restrict__ Wa2,
                                 const float* __restrict__ Wp2, const float* __restrict__ bp2)
{
    int id = blockIdx.x*256 + threadIdx.x;
    if (id < C23_T0) {
        g_Wa2h[id] = __float2bfloat16(Wa2[id]);
        return;
    }
    if (id < C23_T1) {
        int r = id - C23_T0;
        int j = r >> 6, t = r & 63;
        float s = 0.f;
        #pragma unroll 4
        for (int c = 0; c < Dc; c++) s = fmaf(g_Wa1f[j*Dc + c], Wp2[c*PHc + t], s);
        g_W12h[r] = __float2bfloat16(s);
        return;
    }
    if (id < C23_T2) {
        int r = id - C23_T1;
        int which = r / (AHc*CINc);
        int rr = r % (AHc*CINc);
        int j = rr >> 7, c = rr & 127;
        const float* W = which ? g_Wk : g_Wq;
        float s = 0.f;
        #pragma unroll 4
        for (int t = 0; t < Dc; t++) s = fmaf(g_Wa1f[j*Dc + t], W[t*CINc + c], s);
        (which ? g_WAK : g_WAQ)[rr] = __float2bfloat16(s);
        return;
    }
    if (id < C23_T3) {
        int j = id - C23_T2;
        float s = g_ba1f[j];
        #pragma unroll 4
        for (int c = 0; c < Dc; c++) s = fmaf(g_Wa1f[j*Dc + c], bp2[c], s);
        g_b1p[j] = s;
        return;
    }
    if (id < C23_T4) {
        int j = id - C23_T3;
        float s = 0.f;
        #pragma unroll 4
        for (int t = 0; t < Dc; t++) s = fmaf(g_Wa1f[j*Dc + t], g_bq2[t] - g_bk2[t], s);
        g_bqk[j] = s;
    }
}

// ---------------- KNN part 1 ----------------
__global__ void knn_part_kernel(const float* __restrict__ pos)
{
    __shared__ __align__(16) float4 sc[CH];
    int b = blockIdx.z, ch = blockIdx.y;
    int tid = threadIdx.x;
    int c0 = ch * CH;
    for (int q = tid; q < CH; q += 128) {
        float x = pos[(b*3+0)*Nc + c0 + q];
        float y = pos[(b*3+1)*Nc + c0 + q];
        float z = pos[(b*3+2)*Nc + c0 + q];
        sc[q] = make_float4(x, y, z, fmaf(z, z, fmaf(y, y, x*x)));
    }
    __syncthreads();
    int n = blockIdx.x*128 + tid;
    float qx = pos[(b*3+0)*Nc + n];
    float qy = pos[(b*3+1)*Nc + n];
    float qz = pos[(b*3+2)*Nc + n];
    float qs = fmaf(qz, qz, fmaf(qy, qy, qx*qx));

    float bd[16]; int bi[16];
    #pragma unroll
    for (int t = 0; t < 16; t++) { bd[t] = 3.4e38f; bi[t] = 0; }
    float mx = 3.4e38f; int mp = 0;
    for (int m = 0; m < CH; m++) {
        float4 c = sc[m];
        float dot = fmaf(qz, c.z, fmaf(qy, c.y, qx*c.x));
        float d = (qs + c.w) - 2.0f*dot;
        if (d < mx) {
            bd[mp] = d; bi[mp] = c0 + m;
            mx = bd[0]; mp = 0;
            #pragma unroll
            for (int t = 1; t < 16; t++) if (bd[t] > mx) { mx = bd[t]; mp = t; }
        }
    }
    size_t base = ((size_t)(b*NCH + ch)*Nc + n)*16;
    #pragma unroll
    for (int t = 0; t < 16; t++) { g_pd[base + t] = bd[t]; g_pi[base + t] = bi[t]; }
}

// ---------------- KNN part 2: merge ----------------
__global__ void knn_merge_kernel()
{
    int id = blockIdx.x*256 + threadIdx.x;
    int b = id >> 12, n = id & (Nc-1);
    float bd[16]; int bi[16];
    #pragma unroll
    for (int t = 0; t < 16; t++) { bd[t] = 3.4e38f; bi[t] = 0; }
    float mx = 3.4e38f; int mp = 0;
    for (int ch = 0; ch < NCH; ch++) {
        size_t base = ((size_t)(b*NCH + ch)*Nc + n)*16;
        #pragma unroll
        for (int t = 0; t < 16; t++) {
            float d = g_pd[base + t];
            if (d < mx) {
                bd[mp] = d; bi[mp] = g_pi[base + t];
                mx = bd[0]; mp = 0;
                #pragma unroll
                for (int u = 1; u < 16; u++) if (bd[u] > mx) { mx = bd[u]; mp = u; }
            }
        }
    }
    #pragma unroll
    for (int t = 0; t < 16; t++) g_idx[(b*Nc+n)*16 + t] = bi[t];
}

// ---------------- tiled fp32 GEMM (value conv; channel-major input) ----------------
template<int O, int I, bool POINT_MAJOR>
__global__ void gemm_kernel(const float* __restrict__ W, const float* __restrict__ bias,
                            const float* __restrict__ In, float* __restrict__ Out)
{
    __shared__ float Wt[64][33];
    __shared__ float Xt[32][64];
    int b  = blockIdx.z;
    int n0 = blockIdx.x*64, o0 = blockIdx.y*64;
    int tid = threadIdx.x, tx = tid & 15, ty = tid >> 4;
    float acc[4][4];
    #pragma unroll
    for (int r = 0; r < 4; r++)
        #pragma unroll
        for (int c = 0; c < 4; c++) acc[r][c] = 0.f;

    for (int k0 = 0; k0 < I; k0 += 32) {
        for (int q = tid; q < 64*32; q += 256) {
            int oo = q >> 5, kk = q & 31;
            Wt[oo][kk] = W[(o0+oo)*I + k0 + kk];
        }
        for (int q = tid; q < 32*64; q += 256) {
            int kk = q >> 6, nn = q & 63;
            Xt[kk][nn] = In[((size_t)b*I + k0 + kk)*Nc + n0 + nn];
        }
        __syncthreads();
        #pragma unroll 8
        for (int kk = 0; kk < 32; kk++) {
            float a[4], bb[4];
            #pragma unroll
            for (int r = 0; r < 4; r++) a[r]  = Wt[ty*4+r][kk];
            #pragma unroll
            for (int c = 0; c < 4; c++) bb[c] = Xt[kk][tx*4+c];
            #pragma unroll
            for (int r = 0; r < 4; r++)
                #pragma unroll
                for (int c = 0; c < 4; c++) acc[r][c] = fmaf(a[r], bb[c], acc[r][c]);
        }
        __syncthreads();
    }
    #pragma unroll
    for (int r = 0; r < 4; r++) {
        float bv = bias[o0 + ty*4 + r];
        #pragma unroll
        for (int c = 0; c < 4; c++) {
            float v = acc[r][c] + bv;
            int oo = o0 + ty*4 + r, nn = n0 + tx*4 + c;
            if (POINT_MAJOR)
                Out[((size_t)b*Nc + nn)*O + oo] = v;
            else
                Out[((size_t)b*O + oo)*Nc + nn] = v;
        }
    }
}

// ---------------- final GEMM: In is POINT-major (b,n,I); Out channel-major (b,O,n) ----------------
__global__ void final_gemm_kernel(const float* __restrict__ W, const float* __restrict__ bias,
                                  const float* __restrict__ In, float* __restrict__ Out)
{
    const int O = CINc, I = Dc;
    __shared__ float Wt[64][33];
    __shared__ float Xt[32][65];
    int b  = blockIdx.z;
    int n0 = blockIdx.x*64, o0 = blockIdx.y*64;
    int tid = threadIdx.x, tx = tid & 15, ty = tid >> 4;
    float acc[4][4];
    #pragma unroll
    for (int r = 0; r < 4; r++)
        #pragma unroll
        for (int c = 0; c < 4; c++) acc[r][c] = 0.f;

    for (int k0 = 0; k0 < I; k0 += 32) {
        for (int q = tid; q < 64*32; q += 256) {
            int oo = q >> 5, kk = q & 31;
            Wt[oo][kk] = W[(o0+oo)*I + k0 + kk];
        }
        for (int q = tid; q < 64*32; q += 256) {
            int nn = q >> 5, kk = q & 31;
            Xt[kk][nn] = In[((size_t)b*Nc + n0 + nn)*I + k0 + kk];
        }
        __syncthreads();
        #pragma unroll 8
        for (int kk = 0; kk < 32; kk++) {
            float a[4], bb[4];
            #pragma unroll
            for (int r = 0; r < 4; r++) a[r]  = Wt[ty*4+r][kk];
            #pragma unroll
            for (int c = 0; c < 4; c++) bb[c] = Xt[kk][tx*4+c];
            #pragma unroll
            for (int r = 0; r < 4; r++)
                #pragma unroll
                for (int c = 0; c < 4; c++) acc[r][c] = fmaf(a[r], bb[c], acc[r][c]);
        }
        __syncthreads();
    }
    #pragma unroll
    for (int r = 0; r < 4; r++) {
        float bv = bias[o0 + ty*4 + r];
        #pragma unroll
        for (int c = 0; c < 4; c++) {
            int oo = o0 + ty*4 + r, nn = n0 + tx*4 + c;
            Out[((size_t)b*O + oo)*Nc + nn] = acc[r][c] + bv;
        }
    }
}

// ---------------- build: pos-MLP hidden h (bf16) + PE (fp32) ----------------
__global__ void build_kernel(const float* __restrict__ pos,
                             const float* __restrict__ Wp2,
                             const float* __restrict__ bp2)
{
    __shared__ float pr[3][64];
    __shared__ __align__(16) float sh[PHc*64];
    __shared__ int sidx[64];
    int b = blockIdx.y;
    int nbase = blockIdx.x*4;
    int pbase = nbase*16;
    int tid = threadIdx.x;

    if (tid < 64) sidx[tid] = g_idx[(b*Nc + nbase)*16 + tid];
    __syncthreads();
    if (tid < 192) {
        int d = tid >> 6, pp = tid & 63;
        int n  = nbase + (pp >> 4);
        int nb = sidx[pp];
        pr[d][pp] = pos[(b*3+d)*Nc + n] - pos[(b*3+d)*Nc + nb];
    }
    __syncthreads();
    for (int q = tid; q < PHc*64; q += 256) {
        int j = q >> 6, pp = q & 63;
        float h = fmaf(g_Wp1f[j*3+2], pr[2][pp],
                  fmaf(g_Wp1f[j*3+1], pr[1][pp],
                  fmaf(g_Wp1f[j*3+0], pr[0][pp], g_bp1f[j])));
        sh[q] = fmaxf(h, 0.f);
    }
    __syncthreads();

    for (int q = tid; q < PHc*64; q += 256) {
        int pp = q >> 6, j = q & 63;
        g_hh[((size_t)b*Pc + pbase + pp)*PHc + j] = __float2bfloat16(sh[j*64 + pp]);
    }

    int c = tid;
    float bc = bp2[c];
    ull A[32];
    #pragma unroll
    for (int g = 0; g < 32; g++) A[g] = pk2(bc, bc);
    const ull* HP = (const ull*)sh;
    #pragma unroll 2
    for (int j = 0; j < PHc; j++) {
        float w = Wp2[c*PHc + j];
        ull wb = pk2(w, w);
        const ull* hp = HP + j*32;
        #pragma unroll
        for (int g = 0; g < 32; g++) A[g] = fma2(wb, hp[g], A[g]);
    }
    #pragma unroll
    for (int g = 0; g < 32; g++) {
        float p0, p1; upk2(A[g], p0, p1);
        g_PE[((size_t)b*Pc + pbase + g*2)*Dc + c]     = p0;
        g_PE[((size_t)b*Pc + pbase + g*2 + 1)*Dc + c] = p1;
    }
}

// ---------------- warp-MMA core with 3-stage cp.async pipeline (qkw) ----------------
#define SMPITCH 144
#define ABUF (128*SMPITCH)
#define BBUF (256*SMPITCH)
#define SMEM_MMA (3*(ABUF+BBUF))   /* 165888 B */

template<int KTOT>
__device__ __forceinline__ void mma_core(char* sm,
                                         const __nv_bfloat16* __restrict__ gA,
                                         const __nv_bfloat16* __restrict__ gB,
                                         float (&acc)[16][4])
{
    uint32_t sA = smem_u32(sm);
    uint32_t sB = sA + 3*ABUF;
    int tid = threadIdx.x;
    int lane = tid & 31, wid = tid >> 5;
    int wr = wid >> 1, wc = wid & 1;

    uint32_t aOff = (uint32_t)(wr*16 + (lane & 15))*SMPITCH + (uint32_t)((lane >> 4) << 4);
    uint32_t bOff = (uint32_t)(wc*128 + (lane & 15))*SMPITCH + (uint32_t)((lane >> 4) << 4);

    const int NS = KTOT/64;
    int arow = tid >> 3, ac8 = (tid & 7) << 3;
    #define MMA_ISSUE(s, buf) do { \
        uint32_t dA = sA + (buf)*ABUF; \
        uint32_t dB = sB + (buf)*BBUF; \
        _Pragma("unroll") \
        for (int it = 0; it < 2; it++) { \
            int row = arow + it*64; \
            CP_ASYNC16(dA + row*SMPITCH + ac8*2, gA + (size_t)row*KTOT + (s)*64 + ac8); \
        } \
        _Pragma("unroll") \
        for (int it = 0; it < 4; it++) { \
            int row = arow + it*64; \
            CP_ASYNC16(dB + row*SMPITCH + ac8*2, gB + (size_t)row*KTOT + (s)*64 + ac8); \
        } \
        CP_COMMIT(); \
    } while(0)

    MMA_ISSUE(0, 0);
    if (NS > 1) MMA_ISSUE(1, 1);
    int buf = 0;
    for (int i = 0; i < NS; i++) {
        if (i + 2 < NS)      { MMA_ISSUE(i+2, (buf+2 >= 3) ? buf-1 : buf+2); CP_WAIT2(); }
        else if (i + 1 < NS) { CP_WAIT1(); }
        else                 { CP_WAIT0(); }
        __syncthreads();
        uint32_t aAddr = sA + buf*ABUF + aOff;
        uint32_t bAddr = sB + buf*BBUF + bOff;
        #pragma unroll
        for (int ks = 0; ks < 4; ks++) {
            uint32_t a[4];
            LDSM_X4(a, aAddr + ks*32);
            #pragma unroll
            for (int tp = 0; tp < 8; tp++) {
                uint32_t q[4];
                LDSM_X4(q, bAddr + tp*16*SMPITCH + ks*32);
                MMA16816(acc[2*tp],   a, q[0], q[2]);
                MMA16816(acc[2*tp+1], a, q[1], q[3]);
            }
        }
        __syncthreads();
        buf = (buf + 1 >= 3) ? 0 : buf + 1;
    }
    #undef MMA_ISSUE
}

// ---------------- qkw: qW = WAQ·qp (+ b1p + bqk), kW = WAK·obj (K=128), bf16 out ----------------
__global__ void __launch_bounds__(512, 1) qkw_kernel()
{
    extern __shared__ __align__(16) char smq[];
    int z = blockIdx.z;
    int b = z >> 1, which = z & 1;
    int ntile = blockIdx.x*128;
    int j0 = blockIdx.y*256;
    const __nv_bfloat16* gA = (which ? g_qp_h : g_obj_h) + ((size_t)b*Nc + ntile)*CINc;
    const __nv_bfloat16* gB = (which ? g_WAQ : g_WAK) + (size_t)j0*CINc;
    __nv_bfloat16* Out = (which ? g_qWh : g_kWh) + ((size_t)b*Nc)*AHc;

    float acc[16][4];
    #pragma unroll
    for (int t = 0; t < 16; t++)
        #pragma unroll
        for (int q = 0; q < 4; q++) acc[t][q] = 0.f;

    mma_core<CINc>(smq, gA, gB, acc);

    int tid = threadIdx.x, lane = tid & 31, wid = tid >> 5;
    int wr = wid >> 1, wc = wid & 1;
    int row0 = ntile + wr*16 + (lane >> 2);
    __nv_bfloat16* O0 = Out + (size_t)row0*AHc + j0;
    __nv_bfloat16* O1 = O0 + (size_t)8*AHc;
    #pragma unroll
    for (int t = 0; t < 16; t++) {
        int c = wc*128 + t*8 + ((lane & 3) << 1);
        float a0 = acc[t][0], a1 = acc[t][1], a2 = acc[t][2], a3 = acc[t][3];
        if (which) {   // fold per-j biases into the qW table
            int j = j0 + c;
            float bb0 = g_b1p[j]   + g_bqk[j];
            float bb1 = g_b1p[j+1] + g_bqk[j+1];
            a0 += bb0; a1 += bb1; a2 += bb0; a3 += bb1;
        }
        uint32_t u0, u1;
        asm("cvt.rn.bf16x2.f32 %0, %1, %2;" : "=r"(u0) : "f"(a1), "f"(a0));
        asm("cvt.rn.bf16x2.f32 %0, %1, %2;" : "=r"(u1) : "f"(a3), "f"(a2));
        *(uint32_t*)(O0 + c) = u0;
        *(uint32_t*)(O1 + c) = u1;
    }
}

// ---------------- FUSED mlp ----------------
#define PITCH_H 272                 /* 128 bf16 + 8 pad */
#define FA  (128*SMPITCH)
#define FW  (128*SMPITCH)
#define FH  (128*PITCH_H)
#define FB2 (256*PITCH_H)
#define SMEM_FUSED (FA + 2*FW + FH + 2*FB2)   /* 229376 B */

__global__ void __launch_bounds__(512, 1) mlp_fused_kernel()
{
    extern __shared__ __align__(16) char smf[];
    int b = blockIdx.z;
    int ptile = blockIdx.x*128;
    const __nv_bfloat16* gA = g_hh + ((size_t)b*Pc + ptile)*PHc;

    uint32_t sA  = smem_u32(smf);
    uint32_t sW  = sA + FA;
    uint32_t sH  = sW + 2*FW;
    uint32_t sB2 = sH + FH;
    int tid = threadIdx.x;
    int lane = tid & 31, wid = tid >> 5;
    int wr = wid >> 1, wc = wid & 1;

    #define FISSUE(jc_, buf_) do { \
        uint32_t dW = sW + (buf_)*FW; \
        uint32_t dB = sB2 + (buf_)*FB2; \
        int j0_ = (jc_)*128; \
        _Pragma("unroll") \
        for (int it = 0; it < 2; it++) { \
            int u = tid + it*512; int row = u >> 3, c8 = (u & 7) << 3; \
            CP_ASYNC16(dW + row*SMPITCH + c8*2, g_W12h + (size_t)(j0_ + row)*PHc + c8); \
        } \
        _Pragma("unroll") \
        for (int it = 0; it < 8; it++) { \
            int u = tid + it*512; int row = u >> 4, c8 = (u & 15) << 3; \
            CP_ASYNC16(dB + row*PITCH_H + c8*2, g_Wa2h + (size_t)row*AHc + j0_ + c8); \
        } \
        CP_COMMIT(); \
    } while(0)

    {
        #pragma unroll
        for (int it = 0; it < 2; it++) {
            int u = tid + it*512; int row = u >> 3, c8 = (u & 7) << 3;
            CP_ASYNC16(sA + row*SMPITCH + c8*2, gA + (size_t)row*PHc + c8);
        }
    }
    FISSUE(0, 0);
    FISSUE(1, 1);

    float accL[16][4];
    #pragma unroll
    for (int t = 0; t < 16; t++)
        #pragma unroll
        for (int q = 0; q < 4; q++) accL[t][q] = 0.f;

    int n = (ptile >> 4) + wr;
    int k0i = lane >> 2;
    int nb0 = g_idx[(b*Nc + n)*16 + k0i];
    int nb1 = g_idx[(b*Nc + n)*16 + k0i + 8];
    const __nv_bfloat16* qWrow = g_qWh + ((size_t)b*Nc + n)*AHc;
    const __nv_bfloat16* kW0   = g_kWh + ((size_t)b*Nc + nb0)*AHc;
    const __nv_bfloat16* kW1   = g_kWh + ((size_t)b*Nc + nb1)*AHc;

    uint32_t aOff1 = (uint32_t)(wr*16 + (lane & 15))*SMPITCH + (uint32_t)((lane >> 4) << 4);
    uint32_t bOff1 = (uint32_t)(wc*64 + (lane & 15))*SMPITCH + (uint32_t)((lane >> 4) << 4);
    uint32_t aOff2 = (uint32_t)(wr*16 + (lane & 15))*PITCH_H + (uint32_t)((lane >> 4) << 4);
    uint32_t bOff2 = (uint32_t)(wc*128 + (lane & 15))*PITCH_H + (uint32_t)((lane >> 4) << 4);
    uint32_t hRow0 = sH + (uint32_t)(wr*16 + (lane >> 2))*PITCH_H;
    uint32_t hRow1 = hRow0 + 8*PITCH_H;

    for (int jc = 0; jc < 8; jc++) {
        int j0 = jc*128;
        if (jc < 7) CP_WAIT1(); else CP_WAIT0();
        __syncthreads();

        float acc1[8][4];
        #pragma unroll
        for (int t = 0; t < 8; t++)
            #pragma unroll
            for (int q = 0; q < 4; q++) acc1[t][q] = 0.f;
        {
            uint32_t bA = sW + (jc & 1)*FW + bOff1;
            #pragma unroll
            for (int ks = 0; ks < 4; ks++) {
                uint32_t a[4];
                LDSM_X4(a, sA + aOff1 + ks*32);
                #pragma unroll
                for (int tq = 0; tq < 4; tq++) {
                    uint32_t q[4];
                    LDSM_X4(q, bA + tq*16*SMPITCH + ks*32);
                    MMA16816(acc1[2*tq],   a, q[0], q[2]);
                    MMA16816(acc1[2*tq+1], a, q[1], q[3]);
                }
            }
        }
        // epilogue1: + qW(biased) - kW, relu, bf16 -> smem H chunk
        #pragma unroll
        for (int m = 0; m < 8; m++) {
            int jl = wc*64 + (m >> 1)*16 + (m & 1)*8 + ((lane & 3) << 1);
            int j = j0 + jl;
            float2 qw = __bfloat1622float2(*(const __nv_bfloat162*)(qWrow + j));
            float2 k0 = __bfloat1622float2(*(const __nv_bfloat162*)(kW0 + j));
            float2 k1 = __bfloat1622float2(*(const __nv_bfloat162*)(kW1 + j));
            float r00 = fmaxf(acc1[m][0] + qw.x - k0.x, 0.f);
            float r01 = fmaxf(acc1[m][1] + qw.y - k0.y, 0.f);
            float r10 = fmaxf(acc1[m][2] + qw.x - k1.x, 0.f);
            float r11 = fmaxf(acc1[m][3] + qw.y - k1.y, 0.f);
            uint32_t u0, u1;
            asm("cvt.rn.bf16x2.f32 %0, %1, %2;" : "=r"(u0) : "f"(r01), "f"(r00));
            asm("cvt.rn.bf16x2.f32 %0, %1, %2;" : "=r"(u1) : "f"(r11), "f"(r10));
            STS32(hRow0 + jl*2, u0);
            STS32(hRow1 + jl*2, u1);
        }
        __syncthreads();

        {
            uint32_t bA = sB2 + (jc & 1)*FB2 + bOff2;
            #pragma unroll
            for (int ks = 0; ks < 8; ks++) {
                uint32_t a[4];
                LDSM_X4(a, sH + aOff2 + ks*32);
                #pragma unroll
                for (int tp = 0; tp < 8; tp++) {
                    uint32_t q[4];
                    LDSM_X4(q, bA + tp*16*PITCH_H + ks*32);
                    MMA16816(accL[2*tp],   a, q[0], q[2]);
                    MMA16816(accL[2*tp+1], a, q[1], q[3]);
                }
            }
        }
        __syncthreads();
        if (jc + 2 <= 7) FISSUE(jc + 2, jc & 1);
    }
    #undef FISSUE

    const float* peRow = g_PE + ((size_t)b*Pc + ptile + wr*16 + (lane >> 2))*Dc;
    const float* valRow = g_valv + ((size_t)b*Nc + n)*Dc;
    float* aggRow = g_agg + ((size_t)b*Nc + n)*Dc;   // POINT-major output

    #pragma unroll
    for (int t = 0; t < 16; t++) {
        int c = wc*128 + t*8 + ((lane & 3) << 1);
        float m0 = fmaxf(accL[t][0], accL[t][2]);
        float m1 = fmaxf(accL[t][1], accL[t][3]);
        #pragma unroll
        for (int d = 4; d <= 16; d <<= 1) {
            m0 = fmaxf(m0, __shfl_xor_sync(0xffffffffu, m0, d));
            m1 = fmaxf(m1, __shfl_xor_sync(0xffffffffu, m1, d));
        }
        float e0 = __expf(accL[t][0] - m0), e2 = __expf(accL[t][2] - m0);
        float e1 = __expf(accL[t][1] - m1), e3 = __expf(accL[t][3] - m1);
        float s0 = e0 + e2, s1 = e1 + e3;
        #pragma unroll
        for (int d = 4; d <= 16; d <<= 1) {
            s0 += __shfl_xor_sync(0xffffffffu, s0, d);
            s1 += __shfl_xor_sync(0xffffffffu, s1, d);
        }
        float2 p0 = *(const float2*)(peRow + c);
        float2 p1 = *(const float2*)(peRow + 8*Dc + c);
        float a0 = e0*p0.x + e2*p1.x;
        float a1 = e1*p0.y + e3*p1.y;
        #pragma unroll
        for (int d = 4; d <= 16; d <<= 1) {
            a0 += __shfl_xor_sync(0xffffffffu, a0, d);
            a1 += __shfl_xor_sync(0xffffffffu, a1, d);
        }
        if (lane < 4) {
            *(float2*)(aggRow + c) = make_float2(a0/s0 + valRow[c], a1/s1 + valRow[c+1]);
        }
    }
}

// ---------------- launch ----------------
extern "C" void kernel_launch(void* const* d_in, const int* in_sizes, int n_in,
                              void* d_out, int out_size)
{
    const float* obj   = (const float*)d_in[0];
    const float* pos   = (const float*)d_in[1];
    const float* qp    = (const float*)d_in[2];
    const float* W_lsq = (const float*)d_in[3];  const float* b_lsq = (const float*)d_in[4];
    const float* W_lso = (const float*)d_in[5];  const float* b_lso = (const float*)d_in[6];
    const float* Wk    = (const float*)d_in[7];  const float* bk    = (const float*)d_in[8];
    const float* Wq    = (const float*)d_in[9];  const float* bq    = (const float*)d_in[10];
    const float* Wv    = (const float*)d_in[11]; const float* bv    = (const float*)d_in[12];
    const float* Wp1   = (const float*)d_in[13]; const float* bp1   = (const float*)d_in[14];
    const float* g1    = (const float*)d_in[15]; const float* bt1   = (const float*)d_in[16];
    const float* m1    = (const float*)d_in[17]; const float* v1    = (const float*)d_in[18];
    const float* Wp2   = (const float*)d_in[19]; const float* bp2   = (const float*)d_in[20];
    const float* Wa1   = (const float*)d_in[21]; const float* ba1   = (const float*)d_in[22];
    const float* g2    = (const float*)d_in[23]; const float* bt2   = (const float*)d_in[24];
    const float* m2    = (const float*)d_in[25]; const float* v2    = (const float*)d_in[26];
    const float* Wa2   = (const float*)d_in[27]; /* ba2 (d_in[28]) cancels in softmax */
    const float* We    = (const float*)d_in[29]; const float* bfin  = (const float*)d_in[30];
    float* out = (float*)d_out;

    cudaFuncSetAttribute(qkw_kernel,       cudaFuncAttributeMaxDynamicSharedMemorySize, SMEM_MMA);
    cudaFuncSetAttribute(mlp_fused_kernel, cudaFuncAttributeMaxDynamicSharedMemorySize, SMEM_FUSED);

    void *pWv, *pbv, *pval, *pagg;
    cudaGetSymbolAddress(&pWv, g_Wv);   cudaGetSymbolAddress(&pbv, g_bv2);
    cudaGetSymbolAddress(&pval, g_valv); cudaGetSymbolAddress(&pagg, g_agg);

    static cudaStream_t s_knn = nullptr;
    static cudaEvent_t  ev_fork = nullptr, ev_fold = nullptr, ev_join = nullptr;
    if (!s_knn) {
        cudaStreamCreateWithFlags(&s_knn, cudaStreamNonBlocking);
        cudaEventCreateWithFlags(&ev_fork, cudaEventDisableTiming);
        cudaEventCreateWithFlags(&ev_fold, cudaEventDisableTiming);
        cudaEventCreateWithFlags(&ev_join, cudaEventDisableTiming);
    }

    // ---- fork: KNN chain (needs only pos) on side stream ----
    cudaEventRecord(ev_fork, 0);
    cudaStreamWaitEvent(s_knn, ev_fork, 0);
    knn_part_kernel<<<dim3(Nc/128, NCH, Bc), 128, 0, s_knn>>>(pos);
    knn_merge_kernel<<<Bc*Nc/256, 256, 0, s_knn>>>();

    // ---- main stream: input transpose + fused compose (3 GEMMs + biases) ----
    transpose_in_kernel<<<dim3(Nc/32, Bc*2), 256>>>(qp, obj);
    compose_kernel<<<387, 256>>>(Wk, bk, Wq, bq, Wv, bv, W_lsq, b_lsq, W_lso, b_lso);
    fold_kernel<<<1029, 256>>>(Wa1, ba1, g2, bt2, m2, v2, Wp1, bp1, g1, bt1, m1, v1);
    cudaEventRecord(ev_fold, 0);

    // ---- side stream: build (needs g_idx + fold weights) overlaps main GEMMs ----
    cudaStreamWaitEvent(s_knn, ev_fold, 0);
    build_kernel<<<dim3(Nc/4, Bc), 256, 0, s_knn>>>(pos, Wp2, bp2);
    cudaEventRecord(ev_join, s_knn);

    // ---- main stream: merged compose23 + value GEMM + qW/kW ----
    compose23_kernel<<<(C23_T4 + 255)/256, 256>>>(Wa2, Wp2, bp2);
    gemm_kernel<Dc, CINc, true><<<dim3(Nc/64, Dc/64, Bc), 256>>>((const float*)pWv, (const float*)pbv, obj, (float*)pval);
    qkw_kernel<<<dim3(Nc/128, AHc/256, Bc*2), 512, SMEM_MMA>>>();

    // ---- join: fused mlp needs g_hh (build) + g_idx (knn) ----
    cudaStreamWaitEvent(0, ev_join, 0);

    mlp_fused_kernel<<<dim3(Pc/128, 1, Bc), 512, SMEM_FUSED>>>();

    final_gemm_kernel<<<dim3(Nc/64, CINc/64, Bc), 256>>>(We, bfin, (const float*)pagg, out);
}